// round 1
// baseline (speedup 1.0000x reference)
#include <cuda_runtime.h>
#include <math.h>

#define N_NODES 25000
#define N_EDGES 200000
#define E_TOT   (N_EDGES + N_NODES)   // 225000 (self-loops appended)
#define C_HID   128
#define F_BIG   1024                   // 8 heads * 128

// ---------------- device scratch (static globals: allocation-free) ----------
__device__ float g_hw  [N_NODES * F_BIG];   // X @ W result of current layer
__device__ float g_bufA[N_NODES * F_BIG];   // layer-1 output features
__device__ float g_bufB[N_NODES * F_BIG];   // layer-2 output features
__device__ float g_bufC[N_NODES * C_HID];   // layer-3 output features
__device__ float g_als [N_NODES * 8];
__device__ float g_ald [N_NODES * 8];
__device__ float g_nmax[N_NODES * 8];
__device__ float g_nsum[N_NODES * 8];
__device__ float g_eexp[E_TOT * 8];
__device__ int   g_src [E_TOT];
__device__ int   g_dst [E_TOT];

// ---------------- helpers ----------------
__device__ __forceinline__ void atomicMaxF(float* addr, float v) {
    if (v >= 0.f) atomicMax((int*)addr, __float_as_int(v));
    else          atomicMin((unsigned int*)addr, __float_as_uint(v));
}

// ---------------- build concatenated edge list (edges + self loops) --------
__global__ void build_edges_k(const int* __restrict__ ei) {
    int i = blockIdx.x * blockDim.x + threadIdx.x;
    if (i < N_EDGES) {
        g_src[i] = ei[i];
        g_dst[i] = ei[N_EDGES + i];
    } else if (i < E_TOT) {
        int n = i - N_EDGES;
        g_src[i] = n;
        g_dst[i] = n;
    }
}

// ---------------- tiled fp32 GEMM: C[M,N] = A[M,K] @ B[K,N] ----------------
// BM=BN=64, BK=16, 256 threads, 4x4 per thread. N%64==0, K%16==0, M guarded.
__global__ __launch_bounds__(256) void sgemm_k(
    const float* __restrict__ A, const float* __restrict__ B,
    float* __restrict__ C, int M, int N, int K)
{
    __shared__ float As[16][64];
    __shared__ float Bs[16][64];
    int t  = threadIdx.x;
    int tx = t & 15, ty = t >> 4;
    int bm = blockIdx.y * 64, bn = blockIdx.x * 64;

    int aRow = t >> 2;          // 0..63
    int aCol = (t & 3) * 4;     // 0,4,8,12
    int bRow = t >> 4;          // 0..15
    int bCol = (t & 15) * 4;    // 0..60

    bool aValid = (bm + aRow) < M;
    const float* Aptr = A + (size_t)(bm + aRow) * K + aCol;
    const float* Bptr = B + (size_t)bRow * N + bn + bCol;

    float acc[4][4] = {};

    for (int k0 = 0; k0 < K; k0 += 16) {
        float4 av = aValid ? *(const float4*)(Aptr + k0)
                           : make_float4(0.f, 0.f, 0.f, 0.f);
        float4 bv = *(const float4*)(Bptr + (size_t)k0 * N);
        As[aCol + 0][aRow] = av.x;
        As[aCol + 1][aRow] = av.y;
        As[aCol + 2][aRow] = av.z;
        As[aCol + 3][aRow] = av.w;
        *(float4*)&Bs[bRow][bCol] = bv;
        __syncthreads();
#pragma unroll
        for (int kk = 0; kk < 16; kk++) {
            float4 a = *(const float4*)&As[kk][ty * 4];
            float4 b = *(const float4*)&Bs[kk][tx * 4];
            acc[0][0] = fmaf(a.x, b.x, acc[0][0]);
            acc[0][1] = fmaf(a.x, b.y, acc[0][1]);
            acc[0][2] = fmaf(a.x, b.z, acc[0][2]);
            acc[0][3] = fmaf(a.x, b.w, acc[0][3]);
            acc[1][0] = fmaf(a.y, b.x, acc[1][0]);
            acc[1][1] = fmaf(a.y, b.y, acc[1][1]);
            acc[1][2] = fmaf(a.y, b.z, acc[1][2]);
            acc[1][3] = fmaf(a.y, b.w, acc[1][3]);
            acc[2][0] = fmaf(a.z, b.x, acc[2][0]);
            acc[2][1] = fmaf(a.z, b.y, acc[2][1]);
            acc[2][2] = fmaf(a.z, b.z, acc[2][2]);
            acc[2][3] = fmaf(a.z, b.w, acc[2][3]);
            acc[3][0] = fmaf(a.w, b.x, acc[3][0]);
            acc[3][1] = fmaf(a.w, b.y, acc[3][1]);
            acc[3][2] = fmaf(a.w, b.z, acc[3][2]);
            acc[3][3] = fmaf(a.w, b.w, acc[3][3]);
        }
        __syncthreads();
    }
#pragma unroll
    for (int i = 0; i < 4; i++) {
        int r = bm + ty * 4 + i;
        if (r < M) {
#pragma unroll
            for (int j = 0; j < 4; j++)
                C[(size_t)r * N + bn + tx * 4 + j] = acc[i][j];
        }
    }
}

// ---------------- attention dot products: al_s/al_d [N,H] ------------------
template <int H>
__global__ void att_dots_k(const float* __restrict__ hw,
                           const float* __restrict__ a_s,
                           const float* __restrict__ a_d)
{
    int w    = (blockIdx.x * blockDim.x + threadIdx.x) >> 5;
    int lane = threadIdx.x & 31;
    if (w >= N_NODES * H) return;
    int n = w / H, h = w - n * H;
    const float* row = hw + (size_t)n * (H * 128) + h * 128;
    float ss = 0.f, sd = 0.f;
#pragma unroll
    for (int c = lane; c < 128; c += 32) {
        float v = row[c];
        ss = fmaf(v, a_s[h * 128 + c], ss);
        sd = fmaf(v, a_d[h * 128 + c], sd);
    }
#pragma unroll
    for (int o = 16; o; o >>= 1) {
        ss += __shfl_down_sync(0xffffffffu, ss, o);
        sd += __shfl_down_sync(0xffffffffu, sd, o);
    }
    if (lane == 0) {
        g_als[n * H + h] = ss;
        g_ald[n * H + h] = sd;
    }
}

// ---------------- per-layer inits ------------------------------------------
__global__ void init_out_k(float* __restrict__ out, const float* __restrict__ b,
                           int total, int mask)
{
    int i = blockIdx.x * blockDim.x + threadIdx.x;
    if (i < total) out[i] = b[i & mask];
}

__global__ void init_nodes_k(int total) {
    int i = blockIdx.x * blockDim.x + threadIdx.x;
    if (i < total) {
        g_nmax[i] = -INFINITY;
        g_nsum[i] = 0.f;
    }
}

// ---------------- edge pass 1: segment max of leaky logits -----------------
template <int H>
__global__ void edge_max_k() {
    int t = blockIdx.x * blockDim.x + threadIdx.x;
    if (t >= E_TOT * H) return;
    int e = t / H, h = t - e * H;
    int s = g_src[e], d = g_dst[e];
    float v = g_als[s * H + h] + g_ald[d * H + h];
    v = v > 0.f ? v : 0.2f * v;
    atomicMaxF(&g_nmax[d * H + h], v);
}

// ---------------- edge pass 2: exp + segment sum ---------------------------
template <int H>
__global__ void edge_exp_k() {
    int t = blockIdx.x * blockDim.x + threadIdx.x;
    if (t >= E_TOT * H) return;
    int e = t / H, h = t - e * H;
    int s = g_src[e], d = g_dst[e];
    float v = g_als[s * H + h] + g_ald[d * H + h];
    v = v > 0.f ? v : 0.2f * v;
    float ex = __expf(v - g_nmax[d * H + h]);
    g_eexp[e * H + h] = ex;
    atomicAdd(&g_nsum[d * H + h], ex);
}

// ---------------- edge pass 3: weighted aggregation (atomic scatter) -------
template <int H>
__global__ void aggregate_k(const float* __restrict__ hw, float* __restrict__ out) {
    int e = blockIdx.x;
    int s = g_src[e], d = g_dst[e];
    if (H == 8) {
        int t = threadIdx.x;   // 256 threads
#pragma unroll
        for (int k = 0; k < 4; k++) {
            int ch = t + k * 256;
            int h  = ch >> 7;
            float alpha = g_eexp[e * 8 + h] / g_nsum[d * 8 + h];
            atomicAdd(&out[(size_t)d * 1024 + ch], hw[(size_t)s * 1024 + ch] * alpha);
        }
    } else {
        int t = threadIdx.x;   // 128 threads
        float alpha = g_eexp[e] / g_nsum[d];
        atomicAdd(&out[(size_t)d * 128 + t], hw[(size_t)s * 128 + t] * alpha);
    }
}

// ---------------- relu in place --------------------------------------------
__global__ void relu_k(float* __restrict__ p, int n) {
    int i = blockIdx.x * blockDim.x + threadIdx.x;
    if (i < n) p[i] = fmaxf(p[i], 0.f);
}

// ---------------- fused pair-MLP scorer ------------------------------------
__global__ __launch_bounds__(128) void mlp_k(
    const float* __restrict__ h3, const int* __restrict__ liq,
    const int* __restrict__ ing,
    const float* __restrict__ mw1, const float* __restrict__ mb1,
    const float* __restrict__ mw2, const float* __restrict__ mb2,
    const float* __restrict__ mw3, const float* __restrict__ mb3,
    float* __restrict__ outp)
{
    __shared__ float pair[256];
    __shared__ float z1[128];
    __shared__ float z2[64];
    int row = blockIdx.x, t = threadIdx.x;
    int L = liq[row], I = ing[row];
    pair[t]       = h3[(size_t)L * 128 + t];
    pair[128 + t] = h3[(size_t)I * 128 + t];
    __syncthreads();
    float acc = mb1[t];
#pragma unroll 8
    for (int i = 0; i < 256; i++) acc = fmaf(pair[i], mw1[i * 128 + t], acc);
    z1[t] = fmaxf(acc, 0.f);
    __syncthreads();
    if (t < 64) {
        float a2 = mb2[t];
#pragma unroll 8
        for (int i = 0; i < 128; i++) a2 = fmaf(z1[i], mw2[i * 64 + t], a2);
        z2[t] = fmaxf(a2, 0.f);
    }
    __syncthreads();
    if (t < 32) {
        float a3 = fmaf(z2[t], mw3[t], z2[t + 32] * mw3[t + 32]);
#pragma unroll
        for (int o = 16; o; o >>= 1) a3 += __shfl_down_sync(0xffffffffu, a3, o);
        if (t == 0) outp[row] = 1.f / (1.f + expf(-(a3 + mb3[0])));
    }
}

// ---------------- host-side per-layer launcher -----------------------------
static void gat_layer_launch(const float* X, int K, const float* W,
                             const float* a_s, const float* a_d, const float* b,
                             float* hw, float* outbuf, int H, bool do_relu)
{
    int F = H * 128;
    dim3 grid(F / 64, (N_NODES + 63) / 64);
    sgemm_k<<<grid, 256>>>(X, W, hw, N_NODES, F, K);

    int warps = N_NODES * H;
    int attBlocks = (warps * 32 + 255) / 256;
    int outTot = N_NODES * F;
    int nodeTot = N_NODES * H;
    int edgeTot = E_TOT * H;

    if (H == 8) {
        att_dots_k<8><<<attBlocks, 256>>>(hw, a_s, a_d);
        init_out_k<<<(outTot + 255) / 256, 256>>>(outbuf, b, outTot, F - 1);
        init_nodes_k<<<(nodeTot + 255) / 256, 256>>>(nodeTot);
        edge_max_k<8><<<(edgeTot + 255) / 256, 256>>>();
        edge_exp_k<8><<<(edgeTot + 255) / 256, 256>>>();
        aggregate_k<8><<<E_TOT, 256>>>(hw, outbuf);
    } else {
        att_dots_k<1><<<attBlocks, 256>>>(hw, a_s, a_d);
        init_out_k<<<(outTot + 255) / 256, 256>>>(outbuf, b, outTot, F - 1);
        init_nodes_k<<<(nodeTot + 255) / 256, 256>>>(nodeTot);
        edge_max_k<1><<<(edgeTot + 255) / 256, 256>>>();
        edge_exp_k<1><<<(edgeTot + 255) / 256, 256>>>();
        aggregate_k<1><<<E_TOT, 128>>>(hw, outbuf);
    }
    if (do_relu) relu_k<<<(outTot + 255) / 256, 256>>>(outbuf, outTot);
}

extern "C" void kernel_launch(void* const* d_in, const int* in_sizes, int n_in,
                              void* d_out, int out_size)
{
    const float* x   = (const float*)d_in[0];
    const int*   ei  = (const int*)d_in[1];
    const int*   liq = (const int*)d_in[2];
    const int*   ing = (const int*)d_in[3];
    const float* W1  = (const float*)d_in[4];
    const float* as1 = (const float*)d_in[5];
    const float* ad1 = (const float*)d_in[6];
    const float* b1  = (const float*)d_in[7];
    const float* W2  = (const float*)d_in[8];
    const float* as2 = (const float*)d_in[9];
    const float* ad2 = (const float*)d_in[10];
    const float* b2  = (const float*)d_in[11];
    const float* W3  = (const float*)d_in[12];
    const float* as3 = (const float*)d_in[13];
    const float* ad3 = (const float*)d_in[14];
    const float* b3  = (const float*)d_in[15];
    const float* mw1 = (const float*)d_in[16];
    const float* mb1 = (const float*)d_in[17];
    const float* mw2 = (const float*)d_in[18];
    const float* mb2 = (const float*)d_in[19];
    const float* mw3 = (const float*)d_in[20];
    const float* mb3 = (const float*)d_in[21];
    float* outp = (float*)d_out;

    float *hw, *bufA, *bufB, *bufC;
    cudaGetSymbolAddress((void**)&hw,   g_hw);
    cudaGetSymbolAddress((void**)&bufA, g_bufA);
    cudaGetSymbolAddress((void**)&bufB, g_bufB);
    cudaGetSymbolAddress((void**)&bufC, g_bufC);

    build_edges_k<<<(E_TOT + 255) / 256, 256>>>(ei);

    gat_layer_launch(x,    64,   W1, as1, ad1, b1, hw, bufA, 8, true);
    gat_layer_launch(bufA, 1024, W2, as2, ad2, b2, hw, bufB, 8, true);
    gat_layer_launch(bufB, 1024, W3, as3, ad3, b3, hw, bufC, 1, false);

    mlp_k<<<4096, 128>>>(bufC, liq, ing, mw1, mb1, mw2, mb2, mw3, mb3, outp);
}

// round 2
// speedup vs baseline: 1.5392x; 1.5392x over previous
#include <cuda_runtime.h>
#include <math.h>
#include <stdint.h>

#define N_NODES 25000
#define N_EDGES 200000
#define E_TOT   (N_EDGES + N_NODES)   // 225000 (self-loops appended)
#define C_HID   128
#define F_BIG   1024                   // 8 heads * 128

// ---------------- device scratch (static globals: allocation-free) ----------
__device__ float g_hw  [N_NODES * F_BIG];   // X @ W result of current layer
__device__ float g_bufA[N_NODES * F_BIG];   // layer-1 output features
__device__ float g_bufB[N_NODES * F_BIG];   // layer-2 output features
__device__ float g_bufC[N_NODES * C_HID];   // layer-3 output features
__device__ float g_als [N_NODES * 8];
__device__ float g_ald [N_NODES * 8];
__device__ float g_nmax[N_NODES * 8];
__device__ float g_nsum[N_NODES * 8];
__device__ float g_eexp[E_TOT * 8];
__device__ int   g_src [E_TOT];
__device__ int   g_dst [E_TOT];

// ---------------- helpers ----------------
__device__ __forceinline__ void atomicMaxF(float* addr, float v) {
    if (v >= 0.f) atomicMax((int*)addr, __float_as_int(v));
    else          atomicMin((unsigned int*)addr, __float_as_uint(v));
}

__device__ __forceinline__ uint32_t f2tf32(float f) {
    uint32_t u;
    asm("cvt.rna.tf32.f32 %0, %1;" : "=r"(u) : "f"(f));
    return u;
}

// ---------------- build concatenated edge list (edges + self loops) --------
__global__ void build_edges_k(const int* __restrict__ ei) {
    int i = blockIdx.x * blockDim.x + threadIdx.x;
    if (i < N_EDGES) {
        g_src[i] = ei[i];
        g_dst[i] = ei[N_EDGES + i];
    } else if (i < E_TOT) {
        int n = i - N_EDGES;
        g_src[i] = n;
        g_dst[i] = n;
    }
}

// ---------------- TF32 tensor-core GEMM: C[M,N] = A[M,K] @ B[K,N] ----------
// CTA tile 128x128, BK=16, 8 warps (2x4), warp tile 64x32 via m16n8k8 mma.
// Requires N % 128 == 0, K % 16 == 0. M guarded.
__global__ __launch_bounds__(256) void mma_gemm_k(
    const float* __restrict__ A, const float* __restrict__ B,
    float* __restrict__ C, int M, int N, int K)
{
    __shared__ uint32_t As[16][132];   // [k][m], padded
    __shared__ uint32_t Bs[16][132];   // [k][n], padded

    const int t    = threadIdx.x;
    const int bm   = blockIdx.y * 128;
    const int bn   = blockIdx.x * 128;
    const int warp = t >> 5, lane = t & 31;
    const int wm   = (warp >> 2) * 64;   // warp row origin (0 or 64)
    const int wn   = (warp & 3) * 32;    // warp col origin
    const int gid  = lane >> 2;          // 0..7
    const int tg   = lane & 3;           // 0..3

    // staging assignment
    const int arow = t >> 1;             // 0..127
    const int acol = (t & 1) * 8;        // 0 or 8
    const int brow = t >> 4;             // 0..15
    const int bcol = (t & 15) * 8;       // 0..120
    const bool aval = (bm + arow) < M;
    const float* Ap = A + (size_t)(bm + arow) * K + acol;
    const float* Bp = B + (size_t)brow * N + bn + bcol;

    float acc[4][4][4];
#pragma unroll
    for (int i = 0; i < 4; i++)
#pragma unroll
        for (int j = 0; j < 4; j++)
#pragma unroll
            for (int r = 0; r < 4; r++) acc[i][j][r] = 0.f;

    float4 a0v, a1v, b0v, b1v;
    // prefetch k0 = 0
    {
        a0v = aval ? *(const float4*)(Ap + 0) : make_float4(0,0,0,0);
        a1v = aval ? *(const float4*)(Ap + 4) : make_float4(0,0,0,0);
        b0v = *(const float4*)(Bp + 0);
        b1v = *(const float4*)(Bp + 4);
    }

    for (int k0 = 0; k0 < K; k0 += 16) {
        // stage current regs -> smem (convert to tf32)
        As[acol + 0][arow] = f2tf32(a0v.x);
        As[acol + 1][arow] = f2tf32(a0v.y);
        As[acol + 2][arow] = f2tf32(a0v.z);
        As[acol + 3][arow] = f2tf32(a0v.w);
        As[acol + 4][arow] = f2tf32(a1v.x);
        As[acol + 5][arow] = f2tf32(a1v.y);
        As[acol + 6][arow] = f2tf32(a1v.z);
        As[acol + 7][arow] = f2tf32(a1v.w);
        {
            uint4 u0 = make_uint4(f2tf32(b0v.x), f2tf32(b0v.y), f2tf32(b0v.z), f2tf32(b0v.w));
            uint4 u1 = make_uint4(f2tf32(b1v.x), f2tf32(b1v.y), f2tf32(b1v.z), f2tf32(b1v.w));
            *(uint4*)&Bs[brow][bcol]     = u0;
            *(uint4*)&Bs[brow][bcol + 4] = u1;
        }
        __syncthreads();

        // prefetch next tile while computing
        if (k0 + 16 < K) {
            int kn = k0 + 16;
            a0v = aval ? *(const float4*)(Ap + kn)     : make_float4(0,0,0,0);
            a1v = aval ? *(const float4*)(Ap + kn + 4) : make_float4(0,0,0,0);
            b0v = *(const float4*)(Bp + (size_t)kn * N);
            b1v = *(const float4*)(Bp + (size_t)kn * N + 4);
        }

#pragma unroll
        for (int ks = 0; ks < 2; ks++) {
            const int kb = ks * 8;
            uint32_t af[4][4], bf[4][2];
#pragma unroll
            for (int mt = 0; mt < 4; mt++) {
                int r = wm + mt * 16 + gid;
                af[mt][0] = As[kb + tg    ][r];
                af[mt][1] = As[kb + tg    ][r + 8];
                af[mt][2] = As[kb + tg + 4][r];
                af[mt][3] = As[kb + tg + 4][r + 8];
            }
#pragma unroll
            for (int nt = 0; nt < 4; nt++) {
                int c = wn + nt * 8 + gid;
                bf[nt][0] = Bs[kb + tg    ][c];
                bf[nt][1] = Bs[kb + tg + 4][c];
            }
#pragma unroll
            for (int mt = 0; mt < 4; mt++) {
#pragma unroll
                for (int nt = 0; nt < 4; nt++) {
                    asm volatile(
                        "mma.sync.aligned.m16n8k8.row.col.f32.tf32.tf32.f32 "
                        "{%0,%1,%2,%3}, {%4,%5,%6,%7}, {%8,%9}, {%0,%1,%2,%3};\n"
                        : "+f"(acc[mt][nt][0]), "+f"(acc[mt][nt][1]),
                          "+f"(acc[mt][nt][2]), "+f"(acc[mt][nt][3])
                        : "r"(af[mt][0]), "r"(af[mt][1]), "r"(af[mt][2]), "r"(af[mt][3]),
                          "r"(bf[nt][0]), "r"(bf[nt][1]));
                }
            }
        }
        __syncthreads();
    }

    // epilogue
#pragma unroll
    for (int mt = 0; mt < 4; mt++) {
        int r0 = bm + wm + mt * 16 + gid;
#pragma unroll
        for (int nt = 0; nt < 4; nt++) {
            int c = bn + wn + nt * 8 + 2 * tg;
            if (r0 < M)
                *(float2*)&C[(size_t)r0 * N + c] =
                    make_float2(acc[mt][nt][0], acc[mt][nt][1]);
            if (r0 + 8 < M)
                *(float2*)&C[(size_t)(r0 + 8) * N + c] =
                    make_float2(acc[mt][nt][2], acc[mt][nt][3]);
        }
    }
}

// ---------------- attention dot products: al_s/al_d [N,H] ------------------
template <int H>
__global__ void att_dots_k(const float* __restrict__ hw,
                           const float* __restrict__ a_s,
                           const float* __restrict__ a_d)
{
    int w    = (blockIdx.x * blockDim.x + threadIdx.x) >> 5;
    int lane = threadIdx.x & 31;
    if (w >= N_NODES * H) return;
    int n = w / H, h = w - n * H;
    const float* row = hw + (size_t)n * (H * 128) + h * 128;
    float ss = 0.f, sd = 0.f;
#pragma unroll
    for (int c = lane; c < 128; c += 32) {
        float v = row[c];
        ss = fmaf(v, a_s[h * 128 + c], ss);
        sd = fmaf(v, a_d[h * 128 + c], sd);
    }
#pragma unroll
    for (int o = 16; o; o >>= 1) {
        ss += __shfl_down_sync(0xffffffffu, ss, o);
        sd += __shfl_down_sync(0xffffffffu, sd, o);
    }
    if (lane == 0) {
        g_als[n * H + h] = ss;
        g_ald[n * H + h] = sd;
    }
}

// ---------------- per-layer inits (vectorized) -----------------------------
__global__ void init_out_k(float4* __restrict__ out, const float4* __restrict__ b,
                           int total4, int mask4)
{
    int i = blockIdx.x * blockDim.x + threadIdx.x;
    if (i < total4) out[i] = b[i & mask4];
}

__global__ void init_nodes_k(int total) {
    int i = blockIdx.x * blockDim.x + threadIdx.x;
    if (i < total) {
        g_nmax[i] = -INFINITY;
        g_nsum[i] = 0.f;
    }
}

// ---------------- edge pass 1: segment max of leaky logits -----------------
template <int H>
__global__ void edge_max_k() {
    int t = blockIdx.x * blockDim.x + threadIdx.x;
    if (t >= E_TOT * H) return;
    int e = t / H, h = t - e * H;
    int s = g_src[e], d = g_dst[e];
    float v = g_als[s * H + h] + g_ald[d * H + h];
    v = v > 0.f ? v : 0.2f * v;
    atomicMaxF(&g_nmax[d * H + h], v);
}

// ---------------- edge pass 2: exp + segment sum ---------------------------
template <int H>
__global__ void edge_exp_k() {
    int t = blockIdx.x * blockDim.x + threadIdx.x;
    if (t >= E_TOT * H) return;
    int e = t / H, h = t - e * H;
    int s = g_src[e], d = g_dst[e];
    float v = g_als[s * H + h] + g_ald[d * H + h];
    v = v > 0.f ? v : 0.2f * v;
    float ex = __expf(v - g_nmax[d * H + h]);
    g_eexp[e * H + h] = ex;
    atomicAdd(&g_nsum[d * H + h], ex);
}

// ---------------- edge pass 3: weighted aggregation (atomic scatter) -------
template <int H>
__global__ void aggregate_k(const float* __restrict__ hw, float* __restrict__ out) {
    int e = blockIdx.x;
    int s = g_src[e], d = g_dst[e];
    if (H == 8) {
        int t = threadIdx.x;   // 256 threads
#pragma unroll
        for (int k = 0; k < 4; k++) {
            int ch = t + k * 256;
            int h  = ch >> 7;
            float alpha = g_eexp[e * 8 + h] / g_nsum[d * 8 + h];
            atomicAdd(&out[(size_t)d * 1024 + ch], hw[(size_t)s * 1024 + ch] * alpha);
        }
    } else {
        int t = threadIdx.x;   // 128 threads
        float alpha = g_eexp[e] / g_nsum[d];
        atomicAdd(&out[(size_t)d * 128 + t], hw[(size_t)s * 128 + t] * alpha);
    }
}

// ---------------- relu in place (vectorized) -------------------------------
__global__ void relu_k(float4* __restrict__ p, int n4) {
    int i = blockIdx.x * blockDim.x + threadIdx.x;
    if (i < n4) {
        float4 v = p[i];
        v.x = fmaxf(v.x, 0.f); v.y = fmaxf(v.y, 0.f);
        v.z = fmaxf(v.z, 0.f); v.w = fmaxf(v.w, 0.f);
        p[i] = v;
    }
}

// ---------------- fused pair-MLP scorer ------------------------------------
__global__ __launch_bounds__(128) void mlp_k(
    const float* __restrict__ h3, const int* __restrict__ liq,
    const int* __restrict__ ing,
    const float* __restrict__ mw1, const float* __restrict__ mb1,
    const float* __restrict__ mw2, const float* __restrict__ mb2,
    const float* __restrict__ mw3, const float* __restrict__ mb3,
    float* __restrict__ outp)
{
    __shared__ float pair[256];
    __shared__ float z1[128];
    __shared__ float z2[64];
    int row = blockIdx.x, t = threadIdx.x;
    int L = liq[row], I = ing[row];
    pair[t]       = h3[(size_t)L * 128 + t];
    pair[128 + t] = h3[(size_t)I * 128 + t];
    __syncthreads();
    float acc = mb1[t];
#pragma unroll 8
    for (int i = 0; i < 256; i++) acc = fmaf(pair[i], mw1[i * 128 + t], acc);
    z1[t] = fmaxf(acc, 0.f);
    __syncthreads();
    if (t < 64) {
        float a2 = mb2[t];
#pragma unroll 8
        for (int i = 0; i < 128; i++) a2 = fmaf(z1[i], mw2[i * 64 + t], a2);
        z2[t] = fmaxf(a2, 0.f);
    }
    __syncthreads();
    if (t < 32) {
        float a3 = fmaf(z2[t], mw3[t], z2[t + 32] * mw3[t + 32]);
#pragma unroll
        for (int o = 16; o; o >>= 1) a3 += __shfl_down_sync(0xffffffffu, a3, o);
        if (t == 0) outp[row] = 1.f / (1.f + expf(-(a3 + mb3[0])));
    }
}

// ---------------- host-side per-layer launcher -----------------------------
static void gat_layer_launch(const float* X, int K, const float* W,
                             const float* a_s, const float* a_d, const float* b,
                             float* hw, float* outbuf, int H, bool do_relu)
{
    int F = H * 128;
    dim3 grid(F / 128, (N_NODES + 127) / 128);
    mma_gemm_k<<<grid, 256>>>(X, W, hw, N_NODES, F, K);

    int warps = N_NODES * H;
    int attBlocks = (warps * 32 + 255) / 256;
    int outTot = N_NODES * F;
    int nodeTot = N_NODES * H;
    int edgeTot = E_TOT * H;
    int out4 = outTot / 4;

    if (H == 8) {
        att_dots_k<8><<<attBlocks, 256>>>(hw, a_s, a_d);
        init_out_k<<<(out4 + 255) / 256, 256>>>((float4*)outbuf, (const float4*)b, out4, F / 4 - 1);
        init_nodes_k<<<(nodeTot + 255) / 256, 256>>>(nodeTot);
        edge_max_k<8><<<(edgeTot + 255) / 256, 256>>>();
        edge_exp_k<8><<<(edgeTot + 255) / 256, 256>>>();
        aggregate_k<8><<<E_TOT, 256>>>(hw, outbuf);
    } else {
        att_dots_k<1><<<attBlocks, 256>>>(hw, a_s, a_d);
        init_out_k<<<(out4 + 255) / 256, 256>>>((float4*)outbuf, (const float4*)b, out4, F / 4 - 1);
        init_nodes_k<<<(nodeTot + 255) / 256, 256>>>(nodeTot);
        edge_max_k<1><<<(edgeTot + 255) / 256, 256>>>();
        edge_exp_k<1><<<(edgeTot + 255) / 256, 256>>>();
        aggregate_k<1><<<E_TOT, 128>>>(hw, outbuf);
    }
    if (do_relu) relu_k<<<(out4 + 255) / 256, 256>>>((float4*)outbuf, out4);
}

extern "C" void kernel_launch(void* const* d_in, const int* in_sizes, int n_in,
                              void* d_out, int out_size)
{
    const float* x   = (const float*)d_in[0];
    const int*   ei  = (const int*)d_in[1];
    const int*   liq = (const int*)d_in[2];
    const int*   ing = (const int*)d_in[3];
    const float* W1  = (const float*)d_in[4];
    const float* as1 = (const float*)d_in[5];
    const float* ad1 = (const float*)d_in[6];
    const float* b1  = (const float*)d_in[7];
    const float* W2  = (const float*)d_in[8];
    const float* as2 = (const float*)d_in[9];
    const float* ad2 = (const float*)d_in[10];
    const float* b2  = (const float*)d_in[11];
    const float* W3  = (const float*)d_in[12];
    const float* as3 = (const float*)d_in[13];
    const float* ad3 = (const float*)d_in[14];
    const float* b3  = (const float*)d_in[15];
    const float* mw1 = (const float*)d_in[16];
    const float* mb1 = (const float*)d_in[17];
    const float* mw2 = (const float*)d_in[18];
    const float* mb2 = (const float*)d_in[19];
    const float* mw3 = (const float*)d_in[20];
    const float* mb3 = (const float*)d_in[21];
    float* outp = (float*)d_out;

    float *hw, *bufA, *bufB, *bufC;
    cudaGetSymbolAddress((void**)&hw,   g_hw);
    cudaGetSymbolAddress((void**)&bufA, g_bufA);
    cudaGetSymbolAddress((void**)&bufB, g_bufB);
    cudaGetSymbolAddress((void**)&bufC, g_bufC);

    build_edges_k<<<(E_TOT + 255) / 256, 256>>>(ei);

    gat_layer_launch(x,    64,   W1, as1, ad1, b1, hw, bufA, 8, true);
    gat_layer_launch(bufA, 1024, W2, as2, ad2, b2, hw, bufB, 8, true);
    gat_layer_launch(bufB, 1024, W3, as3, ad3, b3, hw, bufC, 1, false);

    mlp_k<<<4096, 128>>>(bufC, liq, ing, mw1, mb1, mw2, mb2, mw3, mb3, outp);
}

// round 3
// speedup vs baseline: 3.1806x; 2.0665x over previous
#include <cuda_runtime.h>
#include <math.h>
#include <stdint.h>

#define N_NODES 25000
#define N_EDGES 200000
#define E_TOT   (N_EDGES + N_NODES)   // 225000 (self-loops appended)
#define C_HID   128
#define F_BIG   1024                   // 8 heads * 128

// ---------------- device scratch (static globals: allocation-free) ----------
__device__ float g_hw  [N_NODES * F_BIG];
__device__ float g_bufA[N_NODES * F_BIG];
__device__ float g_bufB[N_NODES * F_BIG];
__device__ float g_bufC[N_NODES * C_HID];
__device__ float g_als [N_NODES * 8];
__device__ float g_ald [N_NODES * 8];
__device__ int   g_src [E_TOT];
__device__ int   g_dst [E_TOT];
__device__ int   g_rowptr[N_NODES + 1];
__device__ int   g_wptr  [N_NODES];
__device__ int   g_csrc  [E_TOT];

// ---------------- cp.async helpers -----------------------------------------
__device__ __forceinline__ void cpa16(void* sdst, const void* gsrc, int sz) {
    uint32_t sa = (uint32_t)__cvta_generic_to_shared(sdst);
    asm volatile("cp.async.cg.shared.global [%0], [%1], 16, %2;"
                 :: "r"(sa), "l"(gsrc), "r"(sz) : "memory");
}
__device__ __forceinline__ void cpa_commit() {
    asm volatile("cp.async.commit_group;" ::: "memory");
}
template <int W> __device__ __forceinline__ void cpa_wait() {
    asm volatile("cp.async.wait_group %0;" :: "n"(W) : "memory");
}

// ---------------- build concatenated edge list -----------------------------
__global__ void build_edges_k(const int* __restrict__ ei) {
    int i = blockIdx.x * blockDim.x + threadIdx.x;
    if (i < N_EDGES) {
        g_src[i] = ei[i];
        g_dst[i] = ei[N_EDGES + i];
    } else if (i < E_TOT) {
        int n = i - N_EDGES;
        g_src[i] = n;
        g_dst[i] = n;
    }
}

// ---------------- CSR build: zero, hist, scan, scatter ---------------------
__global__ void zero_cnt_k() {
    int i = blockIdx.x * blockDim.x + threadIdx.x;
    if (i < N_NODES) g_wptr[i] = 0;
}
__global__ void hist_k() {
    int e = blockIdx.x * blockDim.x + threadIdx.x;
    if (e < E_TOT) atomicAdd(&g_wptr[g_dst[e]], 1);
}
// single-block exclusive scan of g_wptr -> g_rowptr (and reset g_wptr to offsets)
__global__ __launch_bounds__(1024) void scan_k() {
    __shared__ int warpsum[32];
    __shared__ int s_running;
    int t = threadIdx.x, lane = t & 31, wid = t >> 5;
    if (t == 0) s_running = 0;
    __syncthreads();
    for (int base = 0; base < N_NODES; base += 1024) {
        int idx = base + t;
        int v = (idx < N_NODES) ? g_wptr[idx] : 0;
        // warp inclusive scan
        int incl = v;
#pragma unroll
        for (int off = 1; off < 32; off <<= 1) {
            int y = __shfl_up_sync(0xffffffffu, incl, off);
            if (lane >= off) incl += y;
        }
        if (lane == 31) warpsum[wid] = incl;
        __syncthreads();
        if (wid == 0) {
            int ws = warpsum[lane];
            int wi = ws;
#pragma unroll
            for (int off = 1; off < 32; off <<= 1) {
                int y = __shfl_up_sync(0xffffffffu, wi, off);
                if (lane >= off) wi += y;
            }
            warpsum[lane] = wi - ws;   // exclusive warp offsets
        }
        __syncthreads();
        int run = s_running;
        int excl = incl - v + warpsum[wid];
        if (idx < N_NODES) {
            g_rowptr[idx] = run + excl;
            g_wptr[idx]   = run + excl;
        }
        __syncthreads();
        if (t == 1023) s_running = run + excl + v;
        __syncthreads();
    }
    if (threadIdx.x == 0) g_rowptr[N_NODES] = s_running;
}
__global__ void scatter_k() {
    int e = blockIdx.x * blockDim.x + threadIdx.x;
    if (e < E_TOT) {
        int pos = atomicAdd(&g_wptr[g_dst[e]], 1);
        g_csrc[pos] = g_src[e];
    }
}

// ---------------- TF32 tensor-core GEMM with cp.async 3-stage pipeline ----
// C[M,N] = A[M,K] @ B[K,N]. CTA tile 128x128, BK=16, 8 warps 64x32 each.
// N % 128 == 0, K % 16 == 0, M guarded (zero-fill rows).
#define GSTAGES 3
#define AS_STRIDE 20
#define BS_STRIDE 132
#define AS_TILE (128 * AS_STRIDE)           // 2560 floats
#define BS_TILE (16 * BS_STRIDE)            // 2112 floats
#define GEMM_SMEM_BYTES ((GSTAGES * (AS_TILE + BS_TILE)) * 4)  // 56064

__global__ __launch_bounds__(256, 2) void mma_gemm_k(
    const float* __restrict__ A, const float* __restrict__ B,
    float* __restrict__ C, int M, int N, int K)
{
    extern __shared__ float smem[];
    float* As = smem;                       // [st][128][20]
    float* Bs = smem + GSTAGES * AS_TILE;   // [st][16][132]

    const int t    = threadIdx.x;
    const int bm   = blockIdx.y * 128;
    const int bn   = blockIdx.x * 128;
    const int warp = t >> 5, lane = t & 31;
    const int wm   = (warp >> 2) * 64;
    const int wn   = (warp & 3) * 32;
    const int gid  = lane >> 2;
    const int tg   = lane & 3;

    const int kTiles = K >> 4;

    // load-assignment: 512 16B-chunks for A and for B, 2 each per thread
    auto issue_tile = [&](int kt, int st) {
        float* as = As + st * AS_TILE;
        float* bs = Bs + st * BS_TILE;
#pragma unroll
        for (int q = 0; q < 2; q++) {
            int c = t + q * 256;
            // A chunk
            int arow = c >> 2, ac4 = (c & 3) * 4;
            int grow = bm + arow;
            int sz = (grow < M) ? 16 : 0;
            if (grow >= M) grow = M - 1;
            cpa16(&as[arow * AS_STRIDE + ac4],
                  A + (size_t)grow * K + kt * 16 + ac4, sz);
            // B chunk
            int brow = c >> 5, bc4 = (c & 31) * 4;
            cpa16(&bs[brow * BS_STRIDE + bc4],
                  B + (size_t)(kt * 16 + brow) * N + bn + bc4, 16);
        }
    };

    float acc[4][4][4];
#pragma unroll
    for (int i = 0; i < 4; i++)
#pragma unroll
        for (int j = 0; j < 4; j++)
#pragma unroll
            for (int r = 0; r < 4; r++) acc[i][j][r] = 0.f;

    // prologue: stage first GSTAGES-1 tiles
#pragma unroll
    for (int s = 0; s < GSTAGES - 1; s++) {
        if (s < kTiles) issue_tile(s, s);
        cpa_commit();
    }

    for (int kt = 0; kt < kTiles; kt++) {
        cpa_wait<GSTAGES - 2>();
        __syncthreads();

        int nt = kt + GSTAGES - 1;
        if (nt < kTiles) issue_tile(nt, nt % GSTAGES);
        cpa_commit();

        const float* as = As + (kt % GSTAGES) * AS_TILE;
        const float* bs = Bs + (kt % GSTAGES) * BS_TILE;

#pragma unroll
        for (int ks = 0; ks < 2; ks++) {
            const int kb = ks * 8;
            uint32_t af[4][4], bf[4][2];
#pragma unroll
            for (int mt = 0; mt < 4; mt++) {
                int r = wm + mt * 16 + gid;
                af[mt][0] = __float_as_uint(as[(r)     * AS_STRIDE + kb + tg]);
                af[mt][1] = __float_as_uint(as[(r + 8) * AS_STRIDE + kb + tg]);
                af[mt][2] = __float_as_uint(as[(r)     * AS_STRIDE + kb + tg + 4]);
                af[mt][3] = __float_as_uint(as[(r + 8) * AS_STRIDE + kb + tg + 4]);
            }
#pragma unroll
            for (int ntile = 0; ntile < 4; ntile++) {
                int c = wn + ntile * 8 + gid;
                bf[ntile][0] = __float_as_uint(bs[(kb + tg)     * BS_STRIDE + c]);
                bf[ntile][1] = __float_as_uint(bs[(kb + tg + 4) * BS_STRIDE + c]);
            }
#pragma unroll
            for (int mt = 0; mt < 4; mt++) {
#pragma unroll
                for (int ntile = 0; ntile < 4; ntile++) {
                    asm volatile(
                        "mma.sync.aligned.m16n8k8.row.col.f32.tf32.tf32.f32 "
                        "{%0,%1,%2,%3}, {%4,%5,%6,%7}, {%8,%9}, {%0,%1,%2,%3};\n"
                        : "+f"(acc[mt][ntile][0]), "+f"(acc[mt][ntile][1]),
                          "+f"(acc[mt][ntile][2]), "+f"(acc[mt][ntile][3])
                        : "r"(af[mt][0]), "r"(af[mt][1]), "r"(af[mt][2]), "r"(af[mt][3]),
                          "r"(bf[ntile][0]), "r"(bf[ntile][1]));
                }
            }
        }
        __syncthreads();
    }

    // epilogue
#pragma unroll
    for (int mt = 0; mt < 4; mt++) {
        int r0 = bm + wm + mt * 16 + gid;
#pragma unroll
        for (int ntile = 0; ntile < 4; ntile++) {
            int c = bn + wn + ntile * 8 + 2 * tg;
            if (r0 < M)
                *(float2*)&C[(size_t)r0 * N + c] =
                    make_float2(acc[mt][ntile][0], acc[mt][ntile][1]);
            if (r0 + 8 < M)
                *(float2*)&C[(size_t)(r0 + 8) * N + c] =
                    make_float2(acc[mt][ntile][2], acc[mt][ntile][3]);
        }
    }
}

// ---------------- attention dot products: al_s/al_d [N,H] ------------------
template <int H>
__global__ void att_dots_k(const float* __restrict__ hw,
                           const float* __restrict__ a_s,
                           const float* __restrict__ a_d)
{
    int w    = (blockIdx.x * blockDim.x + threadIdx.x) >> 5;
    int lane = threadIdx.x & 31;
    if (w >= N_NODES * H) return;
    int n = w / H, h = w - n * H;
    const float* row = hw + (size_t)n * (H * 128) + h * 128;
    float ss = 0.f, sd = 0.f;
#pragma unroll
    for (int c = lane; c < 128; c += 32) {
        float v = row[c];
        ss = fmaf(v, a_s[h * 128 + c], ss);
        sd = fmaf(v, a_d[h * 128 + c], sd);
    }
#pragma unroll
    for (int o = 16; o; o >>= 1) {
        ss += __shfl_down_sync(0xffffffffu, ss, o);
        sd += __shfl_down_sync(0xffffffffu, sd, o);
    }
    if (lane == 0) {
        g_als[n * H + h] = ss;
        g_ald[n * H + h] = sd;
    }
}

// ---------------- fused GAT softmax + aggregation, H=8 ---------------------
// one block per dst node, 256 threads, 4 channels each (1024 total)
__global__ __launch_bounds__(256) void gat_fused8_k(
    const float* __restrict__ hw, const float* __restrict__ b,
    float* __restrict__ out, int do_relu)
{
    __shared__ float red[256];
    __shared__ float s_max[8], s_sum[8], s_ald[8];
    __shared__ float s_alpha[32][8];
    __shared__ int   s_srcs[32];

    const int d = blockIdx.x;
    const int t = threadIdx.x;
    const int beg = g_rowptr[d], deg = g_rowptr[d + 1] - beg;
    const int h = t & 7, j = t >> 3;

    if (t < 8) s_ald[t] = g_ald[d * 8 + t];
    __syncthreads();

    // pass 1: per-head max of leaky logits
    float m = -INFINITY;
    for (int i = j; i < deg; i += 32) {
        int s = g_csrc[beg + i];
        float v = g_als[s * 8 + h] + s_ald[h];
        v = v > 0.f ? v : 0.2f * v;
        m = fmaxf(m, v);
    }
    red[t] = m; __syncthreads();
#pragma unroll
    for (int off = 128; off >= 8; off >>= 1) {
        if (t < off) red[t] = fmaxf(red[t], red[t + off]);
        __syncthreads();
    }
    if (t < 8) s_max[t] = red[t];
    __syncthreads();

    // pass 2: per-head sum of exp
    float sum = 0.f;
    for (int i = j; i < deg; i += 32) {
        int s = g_csrc[beg + i];
        float v = g_als[s * 8 + h] + s_ald[h];
        v = v > 0.f ? v : 0.2f * v;
        sum += __expf(v - s_max[h]);
    }
    red[t] = sum; __syncthreads();
#pragma unroll
    for (int off = 128; off >= 8; off >>= 1) {
        if (t < off) red[t] += red[t + off];
        __syncthreads();
    }
    if (t < 8) s_sum[t] = red[t];
    __syncthreads();

    // pass 3: aggregate, chunks of 32 edges
    float a0 = 0.f, a1 = 0.f, a2 = 0.f, a3 = 0.f;
    for (int c0 = 0; c0 < deg; c0 += 32) {
        int cn = min(32, deg - c0);
        if (j < cn) {
            int s = g_csrc[beg + c0 + j];
            if (h == 0) s_srcs[j] = s;
            float v = g_als[s * 8 + h] + s_ald[h];
            v = v > 0.f ? v : 0.2f * v;
            s_alpha[j][h] = __expf(v - s_max[h]) / s_sum[h];
        }
        __syncthreads();
        for (int i = 0; i < cn; i++) {
            const float* hr = hw + (size_t)s_srcs[i] * 1024;
            a0 = fmaf(hr[t      ], s_alpha[i][(t      ) >> 7], a0);
            a1 = fmaf(hr[t + 256], s_alpha[i][(t + 256) >> 7], a1);
            a2 = fmaf(hr[t + 512], s_alpha[i][(t + 512) >> 7], a2);
            a3 = fmaf(hr[t + 768], s_alpha[i][(t + 768) >> 7], a3);
        }
        __syncthreads();
    }

    float* orow = out + (size_t)d * 1024;
    a0 += b[t];       a1 += b[t + 256];
    a2 += b[t + 512]; a3 += b[t + 768];
    if (do_relu) {
        a0 = fmaxf(a0, 0.f); a1 = fmaxf(a1, 0.f);
        a2 = fmaxf(a2, 0.f); a3 = fmaxf(a3, 0.f);
    }
    orow[t] = a0; orow[t + 256] = a1; orow[t + 512] = a2; orow[t + 768] = a3;
}

// ---------------- fused GAT softmax + aggregation, H=1 ---------------------
__global__ __launch_bounds__(128) void gat_fused1_k(
    const float* __restrict__ hw, const float* __restrict__ b,
    float* __restrict__ out)
{
    __shared__ float red[128];
    __shared__ float s_alpha[32];
    __shared__ int   s_srcs[32];

    const int d = blockIdx.x;
    const int t = threadIdx.x;
    const int beg = g_rowptr[d], deg = g_rowptr[d + 1] - beg;
    const float ald = g_ald[d];

    float m = -INFINITY;
    for (int i = t; i < deg; i += 128) {
        float v = g_als[g_csrc[beg + i]] + ald;
        v = v > 0.f ? v : 0.2f * v;
        m = fmaxf(m, v);
    }
    red[t] = m; __syncthreads();
#pragma unroll
    for (int off = 64; off >= 1; off >>= 1) {
        if (t < off) red[t] = fmaxf(red[t], red[t + off]);
        __syncthreads();
    }
    const float mx = red[0];
    __syncthreads();

    float sum = 0.f;
    for (int i = t; i < deg; i += 128) {
        float v = g_als[g_csrc[beg + i]] + ald;
        v = v > 0.f ? v : 0.2f * v;
        sum += __expf(v - mx);
    }
    red[t] = sum; __syncthreads();
#pragma unroll
    for (int off = 64; off >= 1; off >>= 1) {
        if (t < off) red[t] += red[t + off];
        __syncthreads();
    }
    const float sm = red[0];
    __syncthreads();

    float acc = 0.f;
    for (int c0 = 0; c0 < deg; c0 += 32) {
        int cn = min(32, deg - c0);
        if (t < cn) {
            int s = g_csrc[beg + c0 + t];
            s_srcs[t] = s;
            float v = g_als[s] + ald;
            v = v > 0.f ? v : 0.2f * v;
            s_alpha[t] = __expf(v - mx) / sm;
        }
        __syncthreads();
        for (int i = 0; i < cn; i++)
            acc = fmaf(hw[(size_t)s_srcs[i] * 128 + t], s_alpha[i], acc);
        __syncthreads();
    }
    out[(size_t)d * 128 + t] = acc + b[t];
}

// ---------------- fused pair-MLP scorer ------------------------------------
__global__ __launch_bounds__(128) void mlp_k(
    const float* __restrict__ h3, const int* __restrict__ liq,
    const int* __restrict__ ing,
    const float* __restrict__ mw1, const float* __restrict__ mb1,
    const float* __restrict__ mw2, const float* __restrict__ mb2,
    const float* __restrict__ mw3, const float* __restrict__ mb3,
    float* __restrict__ outp)
{
    __shared__ float pair[256];
    __shared__ float z1[128];
    __shared__ float z2[64];
    int row = blockIdx.x, t = threadIdx.x;
    int L = liq[row], I = ing[row];
    pair[t]       = h3[(size_t)L * 128 + t];
    pair[128 + t] = h3[(size_t)I * 128 + t];
    __syncthreads();
    float acc = mb1[t];
#pragma unroll 8
    for (int i = 0; i < 256; i++) acc = fmaf(pair[i], mw1[i * 128 + t], acc);
    z1[t] = fmaxf(acc, 0.f);
    __syncthreads();
    if (t < 64) {
        float a2 = mb2[t];
#pragma unroll 8
        for (int i = 0; i < 128; i++) a2 = fmaf(z1[i], mw2[i * 64 + t], a2);
        z2[t] = fmaxf(a2, 0.f);
    }
    __syncthreads();
    if (t < 32) {
        float a3 = fmaf(z2[t], mw3[t], z2[t + 32] * mw3[t + 32]);
#pragma unroll
        for (int o = 16; o; o >>= 1) a3 += __shfl_down_sync(0xffffffffu, a3, o);
        if (t == 0) outp[row] = 1.f / (1.f + expf(-(a3 + mb3[0])));
    }
}

// ---------------- host-side per-layer launcher -----------------------------
static void gat_layer_launch(const float* X, int K, const float* W,
                             const float* a_s, const float* a_d, const float* b,
                             float* hw, float* outbuf, int H, bool do_relu)
{
    int F = H * 128;
    dim3 grid(F / 128, (N_NODES + 127) / 128);
    mma_gemm_k<<<grid, 256, GEMM_SMEM_BYTES>>>(X, W, hw, N_NODES, F, K);

    int warps = N_NODES * H;
    int attBlocks = (warps * 32 + 255) / 256;
    if (H == 8) {
        att_dots_k<8><<<attBlocks, 256>>>(hw, a_s, a_d);
        gat_fused8_k<<<N_NODES, 256>>>(hw, b, outbuf, do_relu ? 1 : 0);
    } else {
        att_dots_k<1><<<attBlocks, 256>>>(hw, a_s, a_d);
        gat_fused1_k<<<N_NODES, 128>>>(hw, b, outbuf);
    }
}

extern "C" void kernel_launch(void* const* d_in, const int* in_sizes, int n_in,
                              void* d_out, int out_size)
{
    const float* x   = (const float*)d_in[0];
    const int*   ei  = (const int*)d_in[1];
    const int*   liq = (const int*)d_in[2];
    const int*   ing = (const int*)d_in[3];
    const float* W1  = (const float*)d_in[4];
    const float* as1 = (const float*)d_in[5];
    const float* ad1 = (const float*)d_in[6];
    const float* b1  = (const float*)d_in[7];
    const float* W2  = (const float*)d_in[8];
    const float* as2 = (const float*)d_in[9];
    const float* ad2 = (const float*)d_in[10];
    const float* b2  = (const float*)d_in[11];
    const float* W3  = (const float*)d_in[12];
    const float* as3 = (const float*)d_in[13];
    const float* ad3 = (const float*)d_in[14];
    const float* b3  = (const float*)d_in[15];
    const float* mw1 = (const float*)d_in[16];
    const float* mb1 = (const float*)d_in[17];
    const float* mw2 = (const float*)d_in[18];
    const float* mb2 = (const float*)d_in[19];
    const float* mw3 = (const float*)d_in[20];
    const float* mb3 = (const float*)d_in[21];
    float* outp = (float*)d_out;

    static bool attr_set = false;
    cudaFuncSetAttribute(mma_gemm_k,
                         cudaFuncAttributeMaxDynamicSharedMemorySize,
                         GEMM_SMEM_BYTES);
    (void)attr_set;

    float *hw, *bufA, *bufB, *bufC;
    cudaGetSymbolAddress((void**)&hw,   g_hw);
    cudaGetSymbolAddress((void**)&bufA, g_bufA);
    cudaGetSymbolAddress((void**)&bufB, g_bufB);
    cudaGetSymbolAddress((void**)&bufC, g_bufC);

    // edge list + CSR (by dst) build
    build_edges_k<<<(E_TOT + 255) / 256, 256>>>(ei);
    zero_cnt_k<<<(N_NODES + 255) / 256, 256>>>();
    hist_k<<<(E_TOT + 255) / 256, 256>>>();
    scan_k<<<1, 1024>>>();
    scatter_k<<<(E_TOT + 255) / 256, 256>>>();

    gat_layer_launch(x,    64,   W1, as1, ad1, b1, hw, bufA, 8, true);
    gat_layer_launch(bufA, 1024, W2, as2, ad2, b2, hw, bufB, 8, true);
    gat_layer_launch(bufB, 1024, W3, as3, ad3, b3, hw, bufC, 1, false);

    mlp_k<<<4096, 128>>>(bufC, liq, ing, mw1, mb1, mw2, mb2, mw3, mb3, outp);
}

// round 4
// speedup vs baseline: 3.2783x; 1.0307x over previous
#include <cuda_runtime.h>
#include <math.h>
#include <stdint.h>

#define N_NODES 25000
#define N_EDGES 200000
#define E_TOT   (N_EDGES + N_NODES)   // 225000 (self-loops appended)
#define C_HID   128
#define F_BIG   1024                   // 8 heads * 128
#define NBLK    ((N_NODES + 1023) / 1024)   // 25

// ---------------- device scratch (static globals: allocation-free) ----------
__device__ float g_hw  [N_NODES * F_BIG];
__device__ float g_bufA[N_NODES * F_BIG];
__device__ float g_bufB[N_NODES * F_BIG];
__device__ float g_bufC[N_NODES * C_HID];
__device__ float g_als [N_NODES * 8];
__device__ float g_ald [N_NODES * 8];
__device__ int   g_src [E_TOT];
__device__ int   g_dst [E_TOT];
__device__ int   g_rowptr[N_NODES + 1];
__device__ int   g_wptr  [N_NODES];
__device__ int   g_csrc  [E_TOT];
__device__ int   g_bsum  [NBLK];

// ---------------- cp.async helpers -----------------------------------------
__device__ __forceinline__ void cpa16(void* sdst, const void* gsrc, int sz) {
    uint32_t sa = (uint32_t)__cvta_generic_to_shared(sdst);
    asm volatile("cp.async.cg.shared.global [%0], [%1], 16, %2;"
                 :: "r"(sa), "l"(gsrc), "r"(sz) : "memory");
}
__device__ __forceinline__ void cpa_commit() {
    asm volatile("cp.async.commit_group;" ::: "memory");
}
template <int W> __device__ __forceinline__ void cpa_wait() {
    asm volatile("cp.async.wait_group %0;" :: "n"(W) : "memory");
}

// ---------------- build edge list + zero counters (fused) ------------------
__global__ void build_zero_k(const int* __restrict__ ei) {
    int i = blockIdx.x * blockDim.x + threadIdx.x;
    if (i < N_NODES) g_wptr[i] = 0;
    if (i < N_EDGES) {
        g_src[i] = ei[i];
        g_dst[i] = ei[N_EDGES + i];
    } else if (i < E_TOT) {
        int n = i - N_EDGES;
        g_src[i] = n;
        g_dst[i] = n;
    }
}

// ---------------- CSR build ------------------------------------------------
__global__ void hist_k() {
    int e = blockIdx.x * blockDim.x + threadIdx.x;
    if (e < E_TOT) atomicAdd(&g_wptr[g_dst[e]], 1);
}

// phase 1: per-block exclusive scan -> g_rowptr (local), block totals
__global__ __launch_bounds__(1024) void scan1_k() {
    __shared__ int ws[32];
    int t = threadIdx.x, lane = t & 31, wid = t >> 5;
    int idx = blockIdx.x * 1024 + t;
    int v = (idx < N_NODES) ? g_wptr[idx] : 0;
    int incl = v;
#pragma unroll
    for (int off = 1; off < 32; off <<= 1) {
        int y = __shfl_up_sync(0xffffffffu, incl, off);
        if (lane >= off) incl += y;
    }
    if (lane == 31) ws[wid] = incl;
    __syncthreads();
    if (wid == 0) {
        int s = ws[lane], si = s;
#pragma unroll
        for (int off = 1; off < 32; off <<= 1) {
            int y = __shfl_up_sync(0xffffffffu, si, off);
            if (lane >= off) si += y;
        }
        ws[lane] = si - s;
    }
    __syncthreads();
    int excl = incl - v + ws[wid];
    if (idx < N_NODES) g_rowptr[idx] = excl;
    if (t == 1023) g_bsum[blockIdx.x] = excl + v;
}
// phase 2: scan block sums (one warp)
__global__ void scan2_k() {
    int lane = threadIdx.x;
    int v = (lane < NBLK) ? g_bsum[lane] : 0;
    int incl = v;
#pragma unroll
    for (int off = 1; off < 32; off <<= 1) {
        int y = __shfl_up_sync(0xffffffffu, incl, off);
        if (lane >= off) incl += y;
    }
    if (lane < NBLK) g_bsum[lane] = incl - v;
}
// phase 3: add offsets, mirror into write pointers
__global__ void scan3_k() {
    int idx = blockIdx.x * 1024 + threadIdx.x;
    if (idx < N_NODES) {
        int val = g_rowptr[idx] + g_bsum[blockIdx.x];
        g_rowptr[idx] = val;
        g_wptr[idx]   = val;
    }
    if (idx == 0) g_rowptr[N_NODES] = E_TOT;
}
__global__ void scatter_k() {
    int e = blockIdx.x * blockDim.x + threadIdx.x;
    if (e < E_TOT) {
        int pos = atomicAdd(&g_wptr[g_dst[e]], 1);
        g_csrc[pos] = g_src[e];
    }
}

// ---------------- TF32 tensor-core GEMM, cp.async 4-stage, fused att-dots --
// C[M,N] = A[M,K] @ B[K,N]; CTA tile 128x128, 8 warps 64x32.
// Epilogue also computes g_als/g_ald = (C-tile rows) . a_s/a_d for the head
// this CTA column covers (BN=128 == one head).
#define GSTAGES 4
#define AS_STRIDE 20
#define BS_STRIDE 132
#define AS_TILE (128 * AS_STRIDE)
#define BS_TILE (16 * BS_STRIDE)
#define GEMM_SMEM_BYTES ((GSTAGES * (AS_TILE + BS_TILE)) * 4)  // 74752

__global__ __launch_bounds__(256, 2) void mma_gemm_k(
    const float* __restrict__ A, const float* __restrict__ B,
    float* __restrict__ C, int M, int N, int K,
    const float* __restrict__ a_s, const float* __restrict__ a_d, int H)
{
    extern __shared__ float smem[];
    float* As = smem;
    float* Bs = smem + GSTAGES * AS_TILE;

    const int t    = threadIdx.x;
    const int bm   = blockIdx.y * 128;
    const int bn   = blockIdx.x * 128;
    const int head = blockIdx.x;          // BN==128 -> one head per CTA col
    const int warp = t >> 5, lane = t & 31;
    const int wm   = (warp >> 2) * 64;
    const int wn   = (warp & 3) * 32;
    const int gid  = lane >> 2;
    const int tg   = lane & 3;

    const int kTiles = K >> 4;

    auto issue_tile = [&](int kt, int st) {
        float* as = As + st * AS_TILE;
        float* bs = Bs + st * BS_TILE;
#pragma unroll
        for (int q = 0; q < 2; q++) {
            int c = t + q * 256;
            int arow = c >> 2, ac4 = (c & 3) * 4;
            int grow = bm + arow;
            int sz = (grow < M) ? 16 : 0;
            if (grow >= M) grow = M - 1;
            cpa16(&as[arow * AS_STRIDE + ac4],
                  A + (size_t)grow * K + kt * 16 + ac4, sz);
            int brow = c >> 5, bc4 = (c & 31) * 4;
            cpa16(&bs[brow * BS_STRIDE + bc4],
                  B + (size_t)(kt * 16 + brow) * N + bn + bc4, 16);
        }
    };

    float acc[4][4][4];
#pragma unroll
    for (int i = 0; i < 4; i++)
#pragma unroll
        for (int j = 0; j < 4; j++)
#pragma unroll
            for (int r = 0; r < 4; r++) acc[i][j][r] = 0.f;

#pragma unroll
    for (int s = 0; s < GSTAGES - 1; s++) {
        if (s < kTiles) issue_tile(s, s);
        cpa_commit();
    }

    for (int kt = 0; kt < kTiles; kt++) {
        cpa_wait<GSTAGES - 2>();
        __syncthreads();

        int nt = kt + GSTAGES - 1;
        if (nt < kTiles) issue_tile(nt, nt % GSTAGES);
        cpa_commit();

        const float* as = As + (kt % GSTAGES) * AS_TILE;
        const float* bs = Bs + (kt % GSTAGES) * BS_TILE;

#pragma unroll
        for (int ks = 0; ks < 2; ks++) {
            const int kb = ks * 8;
            uint32_t af[4][4], bf[4][2];
#pragma unroll
            for (int mt = 0; mt < 4; mt++) {
                int r = wm + mt * 16 + gid;
                af[mt][0] = __float_as_uint(as[(r)     * AS_STRIDE + kb + tg]);
                af[mt][1] = __float_as_uint(as[(r + 8) * AS_STRIDE + kb + tg]);
                af[mt][2] = __float_as_uint(as[(r)     * AS_STRIDE + kb + tg + 4]);
                af[mt][3] = __float_as_uint(as[(r + 8) * AS_STRIDE + kb + tg + 4]);
            }
#pragma unroll
            for (int ntile = 0; ntile < 4; ntile++) {
                int c = wn + ntile * 8 + gid;
                bf[ntile][0] = __float_as_uint(bs[(kb + tg)     * BS_STRIDE + c]);
                bf[ntile][1] = __float_as_uint(bs[(kb + tg + 4) * BS_STRIDE + c]);
            }
#pragma unroll
            for (int mt = 0; mt < 4; mt++) {
#pragma unroll
                for (int ntile = 0; ntile < 4; ntile++) {
                    asm volatile(
                        "mma.sync.aligned.m16n8k8.row.col.f32.tf32.tf32.f32 "
                        "{%0,%1,%2,%3}, {%4,%5,%6,%7}, {%8,%9}, {%0,%1,%2,%3};\n"
                        : "+f"(acc[mt][ntile][0]), "+f"(acc[mt][ntile][1]),
                          "+f"(acc[mt][ntile][2]), "+f"(acc[mt][ntile][3])
                        : "r"(af[mt][0]), "r"(af[mt][1]), "r"(af[mt][2]), "r"(af[mt][3]),
                          "r"(bf[ntile][0]), "r"(bf[ntile][1]));
                }
            }
        }
        __syncthreads();
    }

    // ---- epilogue 1: store C tile ----
#pragma unroll
    for (int mt = 0; mt < 4; mt++) {
        int r0 = bm + wm + mt * 16 + gid;
#pragma unroll
        for (int ntile = 0; ntile < 4; ntile++) {
            int c = bn + wn + ntile * 8 + 2 * tg;
            if (r0 < M)
                *(float2*)&C[(size_t)r0 * N + c] =
                    make_float2(acc[mt][ntile][0], acc[mt][ntile][1]);
            if (r0 + 8 < M)
                *(float2*)&C[(size_t)(r0 + 8) * N + c] =
                    make_float2(acc[mt][ntile][2], acc[mt][ntile][3]);
        }
    }

    // ---- epilogue 2: fused attention dots (row . a_s/a_d over this head) --
    float* s_red = smem;      // reuse stage memory: 256 floats
    s_red[t] = 0.f;
    __syncthreads();

    const float* asv = a_s + head * 128;
    const float* adv = a_d + head * 128;
    float csa[8], cda[8];
#pragma unroll
    for (int ntile = 0; ntile < 4; ntile++) {
        int c = wn + ntile * 8 + 2 * tg;
        csa[ntile * 2]     = asv[c];
        csa[ntile * 2 + 1] = asv[c + 1];
        cda[ntile * 2]     = adv[c];
        cda[ntile * 2 + 1] = adv[c + 1];
    }
#pragma unroll
    for (int mt = 0; mt < 4; mt++) {
#pragma unroll
        for (int half = 0; half < 2; half++) {
            float rs = 0.f, rd = 0.f;
#pragma unroll
            for (int ntile = 0; ntile < 4; ntile++) {
                rs = fmaf(acc[mt][ntile][half * 2],     csa[ntile * 2],     rs);
                rs = fmaf(acc[mt][ntile][half * 2 + 1], csa[ntile * 2 + 1], rs);
                rd = fmaf(acc[mt][ntile][half * 2],     cda[ntile * 2],     rd);
                rd = fmaf(acc[mt][ntile][half * 2 + 1], cda[ntile * 2 + 1], rd);
            }
            rs += __shfl_xor_sync(0xffffffffu, rs, 1);
            rs += __shfl_xor_sync(0xffffffffu, rs, 2);
            rd += __shfl_xor_sync(0xffffffffu, rd, 1);
            rd += __shfl_xor_sync(0xffffffffu, rd, 2);
            if (tg == 0) {
                int rl = wm + mt * 16 + half * 8 + gid;
                atomicAdd(&s_red[rl * 2],     rs);
                atomicAdd(&s_red[rl * 2 + 1], rd);
            }
        }
    }
    __syncthreads();
    if (t < 128 && bm + t < M) {
        g_als[(bm + t) * H + head] = s_red[t * 2];
        g_ald[(bm + t) * H + head] = s_red[t * 2 + 1];
    }
}

// ---------------- fused GAT softmax + aggregation, H=8 ---------------------
__global__ __launch_bounds__(256) void gat_fused8_k(
    const float* __restrict__ hw, const float* __restrict__ b,
    float* __restrict__ out, int do_relu)
{
    __shared__ float red[256];
    __shared__ float s_max[8], s_sum[8], s_ald[8];
    __shared__ float s_alpha[32][8];
    __shared__ int   s_srcs[32];

    const int d = blockIdx.x;
    const int t = threadIdx.x;
    const int beg = g_rowptr[d], deg = g_rowptr[d + 1] - beg;
    const int h = t & 7, j = t >> 3;

    if (t < 8) s_ald[t] = g_ald[d * 8 + t];
    __syncthreads();

    float m = -INFINITY;
    for (int i = j; i < deg; i += 32) {
        int s = g_csrc[beg + i];
        float v = g_als[s * 8 + h] + s_ald[h];
        v = v > 0.f ? v : 0.2f * v;
        m = fmaxf(m, v);
    }
    red[t] = m; __syncthreads();
#pragma unroll
    for (int off = 128; off >= 8; off >>= 1) {
        if (t < off) red[t] = fmaxf(red[t], red[t + off]);
        __syncthreads();
    }
    if (t < 8) s_max[t] = red[t];
    __syncthreads();

    float sum = 0.f;
    for (int i = j; i < deg; i += 32) {
        int s = g_csrc[beg + i];
        float v = g_als[s * 8 + h] + s_ald[h];
        v = v > 0.f ? v : 0.2f * v;
        sum += __expf(v - s_max[h]);
    }
    red[t] = sum; __syncthreads();
#pragma unroll
    for (int off = 128; off >= 8; off >>= 1) {
        if (t < off) red[t] += red[t + off];
        __syncthreads();
    }
    if (t < 8) s_sum[t] = red[t];
    __syncthreads();

    float a0 = 0.f, a1 = 0.f, a2 = 0.f, a3 = 0.f;
    for (int c0 = 0; c0 < deg; c0 += 32) {
        int cn = min(32, deg - c0);
        if (j < cn) {
            int s = g_csrc[beg + c0 + j];
            if (h == 0) s_srcs[j] = s;
            float v = g_als[s * 8 + h] + s_ald[h];
            v = v > 0.f ? v : 0.2f * v;
            s_alpha[j][h] = __expf(v - s_max[h]) / s_sum[h];
        }
        __syncthreads();
        for (int i = 0; i < cn; i++) {
            const float* hr = hw + (size_t)s_srcs[i] * 1024;
            a0 = fmaf(hr[t      ], s_alpha[i][(t      ) >> 7], a0);
            a1 = fmaf(hr[t + 256], s_alpha[i][(t + 256) >> 7], a1);
            a2 = fmaf(hr[t + 512], s_alpha[i][(t + 512) >> 7], a2);
            a3 = fmaf(hr[t + 768], s_alpha[i][(t + 768) >> 7], a3);
        }
        __syncthreads();
    }

    float* orow = out + (size_t)d * 1024;
    a0 += b[t];       a1 += b[t + 256];
    a2 += b[t + 512]; a3 += b[t + 768];
    if (do_relu) {
        a0 = fmaxf(a0, 0.f); a1 = fmaxf(a1, 0.f);
        a2 = fmaxf(a2, 0.f); a3 = fmaxf(a3, 0.f);
    }
    orow[t] = a0; orow[t + 256] = a1; orow[t + 512] = a2; orow[t + 768] = a3;
}

// ---------------- fused GAT softmax + aggregation, H=1 ---------------------
__global__ __launch_bounds__(128) void gat_fused1_k(
    const float* __restrict__ hw, const float* __restrict__ b,
    float* __restrict__ out)
{
    __shared__ float red[128];
    __shared__ float s_alpha[32];
    __shared__ int   s_srcs[32];

    const int d = blockIdx.x;
    const int t = threadIdx.x;
    const int beg = g_rowptr[d], deg = g_rowptr[d + 1] - beg;
    const float ald = g_ald[d];

    float m = -INFINITY;
    for (int i = t; i < deg; i += 128) {
        float v = g_als[g_csrc[beg + i]] + ald;
        v = v > 0.f ? v : 0.2f * v;
        m = fmaxf(m, v);
    }
    red[t] = m; __syncthreads();
#pragma unroll
    for (int off = 64; off >= 1; off >>= 1) {
        if (t < off) red[t] = fmaxf(red[t], red[t + off]);
        __syncthreads();
    }
    const float mx = red[0];
    __syncthreads();

    float sum = 0.f;
    for (int i = t; i < deg; i += 128) {
        float v = g_als[g_csrc[beg + i]] + ald;
        v = v > 0.f ? v : 0.2f * v;
        sum += __expf(v - mx);
    }
    red[t] = sum; __syncthreads();
#pragma unroll
    for (int off = 64; off >= 1; off >>= 1) {
        if (t < off) red[t] += red[t + off];
        __syncthreads();
    }
    const float sm = red[0];
    __syncthreads();

    float acc = 0.f;
    for (int c0 = 0; c0 < deg; c0 += 32) {
        int cn = min(32, deg - c0);
        if (t < cn) {
            int s = g_csrc[beg + c0 + t];
            s_srcs[t] = s;
            float v = g_als[s] + ald;
            v = v > 0.f ? v : 0.2f * v;
            s_alpha[t] = __expf(v - mx) / sm;
        }
        __syncthreads();
        for (int i = 0; i < cn; i++)
            acc = fmaf(hw[(size_t)s_srcs[i] * 128 + t], s_alpha[i], acc);
        __syncthreads();
    }
    out[(size_t)d * 128 + t] = acc + b[t];
}

// ---------------- fused pair-MLP scorer ------------------------------------
__global__ __launch_bounds__(128) void mlp_k(
    const float* __restrict__ h3, const int* __restrict__ liq,
    const int* __restrict__ ing,
    const float* __restrict__ mw1, const float* __restrict__ mb1,
    const float* __restrict__ mw2, const float* __restrict__ mb2,
    const float* __restrict__ mw3, const float* __restrict__ mb3,
    float* __restrict__ outp)
{
    __shared__ float pair[256];
    __shared__ float z1[128];
    __shared__ float z2[64];
    int row = blockIdx.x, t = threadIdx.x;
    int L = liq[row], I = ing[row];
    pair[t]       = h3[(size_t)L * 128 + t];
    pair[128 + t] = h3[(size_t)I * 128 + t];
    __syncthreads();
    float acc = mb1[t];
#pragma unroll 8
    for (int i = 0; i < 256; i++) acc = fmaf(pair[i], mw1[i * 128 + t], acc);
    z1[t] = fmaxf(acc, 0.f);
    __syncthreads();
    if (t < 64) {
        float a2 = mb2[t];
#pragma unroll 8
        for (int i = 0; i < 128; i++) a2 = fmaf(z1[i], mw2[i * 64 + t], a2);
        z2[t] = fmaxf(a2, 0.f);
    }
    __syncthreads();
    if (t < 32) {
        float a3 = fmaf(z2[t], mw3[t], z2[t + 32] * mw3[t + 32]);
#pragma unroll
        for (int o = 16; o; o >>= 1) a3 += __shfl_down_sync(0xffffffffu, a3, o);
        if (t == 0) outp[row] = 1.f / (1.f + expf(-(a3 + mb3[0])));
    }
}

// ---------------- host-side per-layer launcher -----------------------------
static void gat_layer_launch(const float* X, int K, const float* W,
                             const float* a_s, const float* a_d, const float* b,
                             float* hw, float* outbuf, int H, bool do_relu)
{
    int F = H * 128;
    dim3 grid(F / 128, (N_NODES + 127) / 128);
    mma_gemm_k<<<grid, 256, GEMM_SMEM_BYTES>>>(X, W, hw, N_NODES, F, K,
                                               a_s, a_d, H);
    if (H == 8) {
        gat_fused8_k<<<N_NODES, 256>>>(hw, b, outbuf, do_relu ? 1 : 0);
    } else {
        gat_fused1_k<<<N_NODES, 128>>>(hw, b, outbuf);
    }
}

extern "C" void kernel_launch(void* const* d_in, const int* in_sizes, int n_in,
                              void* d_out, int out_size)
{
    const float* x   = (const float*)d_in[0];
    const int*   ei  = (const int*)d_in[1];
    const int*   liq = (const int*)d_in[2];
    const int*   ing = (const int*)d_in[3];
    const float* W1  = (const float*)d_in[4];
    const float* as1 = (const float*)d_in[5];
    const float* ad1 = (const float*)d_in[6];
    const float* b1  = (const float*)d_in[7];
    const float* W2  = (const float*)d_in[8];
    const float* as2 = (const float*)d_in[9];
    const float* ad2 = (const float*)d_in[10];
    const float* b2  = (const float*)d_in[11];
    const float* W3  = (const float*)d_in[12];
    const float* as3 = (const float*)d_in[13];
    const float* ad3 = (const float*)d_in[14];
    const float* b3  = (const float*)d_in[15];
    const float* mw1 = (const float*)d_in[16];
    const float* mb1 = (const float*)d_in[17];
    const float* mw2 = (const float*)d_in[18];
    const float* mb2 = (const float*)d_in[19];
    const float* mw3 = (const float*)d_in[20];
    const float* mb3 = (const float*)d_in[21];
    float* outp = (float*)d_out;

    cudaFuncSetAttribute(mma_gemm_k,
                         cudaFuncAttributeMaxDynamicSharedMemorySize,
                         GEMM_SMEM_BYTES);

    float *hw, *bufA, *bufB, *bufC;
    cudaGetSymbolAddress((void**)&hw,   g_hw);
    cudaGetSymbolAddress((void**)&bufA, g_bufA);
    cudaGetSymbolAddress((void**)&bufB, g_bufB);
    cudaGetSymbolAddress((void**)&bufC, g_bufC);

    // edge list + CSR (by dst) build
    build_zero_k<<<(E_TOT + 255) / 256, 256>>>(ei);
    hist_k<<<(E_TOT + 255) / 256, 256>>>();
    scan1_k<<<NBLK, 1024>>>();
    scan2_k<<<1, 32>>>();
    scan3_k<<<NBLK, 1024>>>();
    scatter_k<<<(E_TOT + 255) / 256, 256>>>();

    gat_layer_launch(x,    64,   W1, as1, ad1, b1, hw, bufA, 8, true);
    gat_layer_launch(bufA, 1024, W2, as2, ad2, b2, hw, bufB, 8, true);
    gat_layer_launch(bufB, 1024, W3, as3, ad3, b3, hw, bufC, 1, false);

    mlp_k<<<4096, 128>>>(bufC, liq, ing, mw1, mb1, mw2, mb2, mw3, mb3, outp);
}

// round 5
// speedup vs baseline: 4.5647x; 1.3924x over previous
#include <cuda_runtime.h>
#include <cuda_bf16.h>
#include <math.h>
#include <stdint.h>

#define N_NODES 25000
#define N_EDGES 200000
#define E_TOT   (N_EDGES + N_NODES)
#define C_HID   128
#define F_BIG   1024
#define NBLK    ((N_NODES + 1023) / 1024)

// ---------------- device scratch -------------------------------------------
__device__ float          g_hw  [N_NODES * F_BIG];      // GEMM C (fp32)
__device__ __nv_bfloat16  g_act [N_NODES * F_BIG];      // activations (GEMM A)
__device__ __nv_bfloat16  g_xb  [N_NODES * 64];         // input x in bf16
__device__ __nv_bfloat16  g_wt1 [1024 * 64];            // W1^T [n][k]
__device__ __nv_bfloat16  g_wt2 [1024 * 1024];          // W2^T
__device__ __nv_bfloat16  g_wt3 [128 * 1024];           // W3^T
__device__ float          g_bufC[N_NODES * C_HID];      // layer-3 out (fp32)
__device__ float g_als [N_NODES * 8];
__device__ float g_ald [N_NODES * 8];
__device__ int   g_src [E_TOT];
__device__ int   g_dst [E_TOT];
__device__ int   g_rowptr[N_NODES + 1];
__device__ int   g_wptr  [N_NODES];
__device__ int   g_csrc  [E_TOT];
__device__ int   g_bsum  [NBLK];

// ---------------- cp.async helpers -----------------------------------------
__device__ __forceinline__ void cpa16(void* sdst, const void* gsrc, int sz) {
    uint32_t sa = (uint32_t)__cvta_generic_to_shared(sdst);
    asm volatile("cp.async.cg.shared.global [%0], [%1], 16, %2;"
                 :: "r"(sa), "l"(gsrc), "r"(sz) : "memory");
}
__device__ __forceinline__ void cpa_commit() {
    asm volatile("cp.async.commit_group;" ::: "memory");
}
template <int W> __device__ __forceinline__ void cpa_wait() {
    asm volatile("cp.async.wait_group %0;" :: "n"(W) : "memory");
}

// ---------------- conversions ----------------------------------------------
__global__ void cvt_x_k(const float* __restrict__ x, int n) {
    int i = blockIdx.x * blockDim.x + threadIdx.x;
    if (i < n) g_xb[i] = __float2bfloat16(x[i]);
}
// W[K][N] fp32 -> Wt[n*K + k] bf16
__global__ void cvt_w_k(const float* __restrict__ W, __nv_bfloat16* __restrict__ Wt,
                        int K, int N) {
    int i = blockIdx.x * blockDim.x + threadIdx.x;
    if (i < K * N) {
        int k = i / N, n = i - k * N;
        Wt[(size_t)n * K + k] = __float2bfloat16(W[i]);
    }
}

// ---------------- edge list + CSR build ------------------------------------
__global__ void build_zero_k(const int* __restrict__ ei) {
    int i = blockIdx.x * blockDim.x + threadIdx.x;
    if (i < N_NODES) g_wptr[i] = 0;
    if (i < N_EDGES) {
        g_src[i] = ei[i];
        g_dst[i] = ei[N_EDGES + i];
    } else if (i < E_TOT) {
        int n = i - N_EDGES;
        g_src[i] = n;
        g_dst[i] = n;
    }
}
__global__ void hist_k() {
    int e = blockIdx.x * blockDim.x + threadIdx.x;
    if (e < E_TOT) atomicAdd(&g_wptr[g_dst[e]], 1);
}
__global__ __launch_bounds__(1024) void scan1_k() {
    __shared__ int ws[32];
    int t = threadIdx.x, lane = t & 31, wid = t >> 5;
    int idx = blockIdx.x * 1024 + t;
    int v = (idx < N_NODES) ? g_wptr[idx] : 0;
    int incl = v;
#pragma unroll
    for (int off = 1; off < 32; off <<= 1) {
        int y = __shfl_up_sync(0xffffffffu, incl, off);
        if (lane >= off) incl += y;
    }
    if (lane == 31) ws[wid] = incl;
    __syncthreads();
    if (wid == 0) {
        int s = ws[lane], si = s;
#pragma unroll
        for (int off = 1; off < 32; off <<= 1) {
            int y = __shfl_up_sync(0xffffffffu, si, off);
            if (lane >= off) si += y;
        }
        ws[lane] = si - s;
    }
    __syncthreads();
    int excl = incl - v + ws[wid];
    if (idx < N_NODES) g_rowptr[idx] = excl;
    if (t == 1023) g_bsum[blockIdx.x] = excl + v;
}
__global__ void scan2_k() {
    int lane = threadIdx.x;
    int v = (lane < NBLK) ? g_bsum[lane] : 0;
    int incl = v;
#pragma unroll
    for (int off = 1; off < 32; off <<= 1) {
        int y = __shfl_up_sync(0xffffffffu, incl, off);
        if (lane >= off) incl += y;
    }
    if (lane < NBLK) g_bsum[lane] = incl - v;
}
__global__ void scan3_k() {
    int idx = blockIdx.x * 1024 + threadIdx.x;
    if (idx < N_NODES) {
        int val = g_rowptr[idx] + g_bsum[blockIdx.x];
        g_rowptr[idx] = val;
        g_wptr[idx]   = val;
    }
    if (idx == 0) g_rowptr[N_NODES] = E_TOT;
}
__global__ void scatter_k() {
    int e = blockIdx.x * blockDim.x + threadIdx.x;
    if (e < E_TOT) {
        int pos = atomicAdd(&g_wptr[g_dst[e]], 1);
        g_csrc[pos] = g_src[e];
    }
}

// ---------------- bf16 tensor-core GEMM, fused attention dots --------------
// C[M,N] = A[M,K] @ Wt[N,K]^T; A,Wt bf16 row-major-by-k. CTA 128x128, BK=16.
// 8 warps, warp tile 64x32, mma.m16n8k16.bf16. Epilogue: C store + als/ald.
#define GSTAGES 4
#define T_STRIDE 24                         // bf16 elems per row (16 + 8 pad)
#define T_TILE   (128 * T_STRIDE)           // 3072 bf16 elems per tile
#define GEMM_SMEM_BYTES (GSTAGES * 2 * T_TILE * 2)   // 49152 B

__global__ __launch_bounds__(256, 2) void mma_gemm_k(
    const __nv_bfloat16* __restrict__ A, const __nv_bfloat16* __restrict__ Bt,
    float* __restrict__ C, int M, int N, int K,
    const float* __restrict__ a_s, const float* __restrict__ a_d, int H)
{
    extern __shared__ __align__(16) __nv_bfloat16 smem_h[];
    __nv_bfloat16* As = smem_h;
    __nv_bfloat16* Bs = smem_h + GSTAGES * T_TILE;

    const int t    = threadIdx.x;
    const int bm   = blockIdx.y * 128;
    const int bn   = blockIdx.x * 128;
    const int head = blockIdx.x;
    const int warp = t >> 5, lane = t & 31;
    const int wm   = (warp >> 2) * 64;
    const int wn   = (warp & 3) * 32;
    const int gid  = lane >> 2;
    const int tg   = lane & 3;

    const int kTiles = K >> 4;

    // staging: A 128 rows x 2 chunks, B 128 rows x 2 chunks; 1 each/thread
    const int srow = t >> 1;
    const int sch  = (t & 1) * 8;           // bf16 elem offset within row
    auto issue_tile = [&](int kt, int st) {
        __nv_bfloat16* as = As + st * T_TILE;
        __nv_bfloat16* bs = Bs + st * T_TILE;
        int grow = bm + srow;
        int sz = (grow < M) ? 16 : 0;
        if (grow >= M) grow = M - 1;
        cpa16(&as[srow * T_STRIDE + sch], A  + (size_t)grow * K + kt * 16 + sch, sz);
        cpa16(&bs[srow * T_STRIDE + sch], Bt + (size_t)(bn + srow) * K + kt * 16 + sch, 16);
    };

    float acc[4][4][4];
#pragma unroll
    for (int i = 0; i < 4; i++)
#pragma unroll
        for (int j = 0; j < 4; j++)
#pragma unroll
            for (int r = 0; r < 4; r++) acc[i][j][r] = 0.f;

#pragma unroll
    for (int s = 0; s < GSTAGES - 1; s++) {
        if (s < kTiles) issue_tile(s, s);
        cpa_commit();
    }

    for (int kt = 0; kt < kTiles; kt++) {
        cpa_wait<GSTAGES - 2>();
        __syncthreads();

        int nt = kt + GSTAGES - 1;
        if (nt < kTiles) issue_tile(nt, nt % GSTAGES);
        cpa_commit();

        const __nv_bfloat16* as = As + (kt % GSTAGES) * T_TILE;
        const __nv_bfloat16* bs = Bs + (kt % GSTAGES) * T_TILE;

        uint32_t af[4][4], bf[4][2];
#pragma unroll
        for (int mt = 0; mt < 4; mt++) {
            int r = wm + mt * 16 + gid;
            af[mt][0] = *(const uint32_t*)&as[(r)     * T_STRIDE + 2 * tg];
            af[mt][1] = *(const uint32_t*)&as[(r + 8) * T_STRIDE + 2 * tg];
            af[mt][2] = *(const uint32_t*)&as[(r)     * T_STRIDE + 2 * tg + 8];
            af[mt][3] = *(const uint32_t*)&as[(r + 8) * T_STRIDE + 2 * tg + 8];
        }
#pragma unroll
        for (int ntile = 0; ntile < 4; ntile++) {
            int c = wn + ntile * 8 + gid;
            bf[ntile][0] = *(const uint32_t*)&bs[c * T_STRIDE + 2 * tg];
            bf[ntile][1] = *(const uint32_t*)&bs[c * T_STRIDE + 2 * tg + 8];
        }
#pragma unroll
        for (int mt = 0; mt < 4; mt++) {
#pragma unroll
            for (int ntile = 0; ntile < 4; ntile++) {
                asm volatile(
                    "mma.sync.aligned.m16n8k16.row.col.f32.bf16.bf16.f32 "
                    "{%0,%1,%2,%3}, {%4,%5,%6,%7}, {%8,%9}, {%0,%1,%2,%3};\n"
                    : "+f"(acc[mt][ntile][0]), "+f"(acc[mt][ntile][1]),
                      "+f"(acc[mt][ntile][2]), "+f"(acc[mt][ntile][3])
                    : "r"(af[mt][0]), "r"(af[mt][1]), "r"(af[mt][2]), "r"(af[mt][3]),
                      "r"(bf[ntile][0]), "r"(bf[ntile][1]));
            }
        }
        __syncthreads();
    }

    // ---- epilogue 1: store C tile (fp32) ----
#pragma unroll
    for (int mt = 0; mt < 4; mt++) {
        int r0 = bm + wm + mt * 16 + gid;
#pragma unroll
        for (int ntile = 0; ntile < 4; ntile++) {
            int c = bn + wn + ntile * 8 + 2 * tg;
            if (r0 < M)
                *(float2*)&C[(size_t)r0 * N + c] =
                    make_float2(acc[mt][ntile][0], acc[mt][ntile][1]);
            if (r0 + 8 < M)
                *(float2*)&C[(size_t)(r0 + 8) * N + c] =
                    make_float2(acc[mt][ntile][2], acc[mt][ntile][3]);
        }
    }

    // ---- epilogue 2: fused attention dots ----
    float* s_red = (float*)smem_h;
    s_red[t] = 0.f;
    __syncthreads();

    const float* asv = a_s + head * 128;
    const float* adv = a_d + head * 128;
    float csa[8], cda[8];
#pragma unroll
    for (int ntile = 0; ntile < 4; ntile++) {
        int c = wn + ntile * 8 + 2 * tg;
        csa[ntile * 2]     = asv[c];
        csa[ntile * 2 + 1] = asv[c + 1];
        cda[ntile * 2]     = adv[c];
        cda[ntile * 2 + 1] = adv[c + 1];
    }
#pragma unroll
    for (int mt = 0; mt < 4; mt++) {
#pragma unroll
        for (int half = 0; half < 2; half++) {
            float rs = 0.f, rd = 0.f;
#pragma unroll
            for (int ntile = 0; ntile < 4; ntile++) {
                rs = fmaf(acc[mt][ntile][half * 2],     csa[ntile * 2],     rs);
                rs = fmaf(acc[mt][ntile][half * 2 + 1], csa[ntile * 2 + 1], rs);
                rd = fmaf(acc[mt][ntile][half * 2],     cda[ntile * 2],     rd);
                rd = fmaf(acc[mt][ntile][half * 2 + 1], cda[ntile * 2 + 1], rd);
            }
            rs += __shfl_xor_sync(0xffffffffu, rs, 1);
            rs += __shfl_xor_sync(0xffffffffu, rs, 2);
            rd += __shfl_xor_sync(0xffffffffu, rd, 1);
            rd += __shfl_xor_sync(0xffffffffu, rd, 2);
            if (tg == 0) {
                int rl = wm + mt * 16 + half * 8 + gid;
                atomicAdd(&s_red[rl * 2],     rs);
                atomicAdd(&s_red[rl * 2 + 1], rd);
            }
        }
    }
    __syncthreads();
    if (t < 128 && bm + t < M) {
        g_als[(bm + t) * H + head] = s_red[t * 2];
        g_ald[(bm + t) * H + head] = s_red[t * 2 + 1];
    }
}

// ---------------- fused GAT softmax + aggregation, H=8 ---------------------
// block per dst node, 256 threads; thread t owns channels 4t..4t+3 (float4).
// Output written as bf16 (next layer's GEMM A), with relu.
__global__ __launch_bounds__(256) void gat_fused8_k(
    const float* __restrict__ hw, const float* __restrict__ b,
    __nv_bfloat16* __restrict__ act)
{
    __shared__ float red[256];
    __shared__ float s_max[8], s_sum[8], s_ald[8];
    __shared__ float s_alpha[32][8];
    __shared__ int   s_srcs[32];

    const int d = blockIdx.x;
    const int t = threadIdx.x;
    const int beg = g_rowptr[d], deg = g_rowptr[d + 1] - beg;
    const int h = t & 7, j = t >> 3;

    if (t < 8) s_ald[t] = g_ald[d * 8 + t];
    __syncthreads();

    float m = -INFINITY;
    for (int i = j; i < deg; i += 32) {
        int s = g_csrc[beg + i];
        float v = g_als[s * 8 + h] + s_ald[h];
        v = v > 0.f ? v : 0.2f * v;
        m = fmaxf(m, v);
    }
    red[t] = m; __syncthreads();
#pragma unroll
    for (int off = 128; off >= 8; off >>= 1) {
        if (t < off) red[t] = fmaxf(red[t], red[t + off]);
        __syncthreads();
    }
    if (t < 8) s_max[t] = red[t];
    __syncthreads();

    float sum = 0.f;
    for (int i = j; i < deg; i += 32) {
        int s = g_csrc[beg + i];
        float v = g_als[s * 8 + h] + s_ald[h];
        v = v > 0.f ? v : 0.2f * v;
        sum += __expf(v - s_max[h]);
    }
    red[t] = sum; __syncthreads();
#pragma unroll
    for (int off = 128; off >= 8; off >>= 1) {
        if (t < off) red[t] += red[t + off];
        __syncthreads();
    }
    if (t < 8) s_sum[t] = red[t];
    __syncthreads();

    const int hh = t >> 5;    // head of channels 4t..4t+3
    float4 a = make_float4(0.f, 0.f, 0.f, 0.f);
    for (int c0 = 0; c0 < deg; c0 += 32) {
        int cn = min(32, deg - c0);
        if (j < cn) {
            int s = g_csrc[beg + c0 + j];
            if (h == 0) s_srcs[j] = s;
            float v = g_als[s * 8 + h] + s_ald[h];
            v = v > 0.f ? v : 0.2f * v;
            s_alpha[j][h] = __expf(v - s_max[h]) / s_sum[h];
        }
        __syncthreads();
        for (int i = 0; i < cn; i++) {
            const float4 hv = *(const float4*)(hw + (size_t)s_srcs[i] * 1024 + 4 * t);
            const float al = s_alpha[i][hh];
            a.x = fmaf(hv.x, al, a.x);
            a.y = fmaf(hv.y, al, a.y);
            a.z = fmaf(hv.z, al, a.z);
            a.w = fmaf(hv.w, al, a.w);
        }
        __syncthreads();
    }

    const float4 bv = ((const float4*)b)[t];
    a.x = fmaxf(a.x + bv.x, 0.f);
    a.y = fmaxf(a.y + bv.y, 0.f);
    a.z = fmaxf(a.z + bv.z, 0.f);
    a.w = fmaxf(a.w + bv.w, 0.f);
    __nv_bfloat162 p0 = __floats2bfloat162_rn(a.x, a.y);
    __nv_bfloat162 p1 = __floats2bfloat162_rn(a.z, a.w);
    uint2 packed = make_uint2(*(uint32_t*)&p0, *(uint32_t*)&p1);
    *(uint2*)&act[(size_t)d * 1024 + 4 * t] = packed;
}

// ---------------- fused GAT softmax + aggregation, H=1 (fp32 out) ----------
__global__ __launch_bounds__(128) void gat_fused1_k(
    const float* __restrict__ hw, const float* __restrict__ b,
    float* __restrict__ out)
{
    __shared__ float red[128];
    __shared__ float s_alpha[32];
    __shared__ int   s_srcs[32];

    const int d = blockIdx.x;
    const int t = threadIdx.x;
    const int beg = g_rowptr[d], deg = g_rowptr[d + 1] - beg;
    const float ald = g_ald[d];

    float m = -INFINITY;
    for (int i = t; i < deg; i += 128) {
        float v = g_als[g_csrc[beg + i]] + ald;
        v = v > 0.f ? v : 0.2f * v;
        m = fmaxf(m, v);
    }
    red[t] = m; __syncthreads();
#pragma unroll
    for (int off = 64; off >= 1; off >>= 1) {
        if (t < off) red[t] = fmaxf(red[t], red[t + off]);
        __syncthreads();
    }
    const float mx = red[0];
    __syncthreads();

    float sum = 0.f;
    for (int i = t; i < deg; i += 128) {
        float v = g_als[g_csrc[beg + i]] + ald;
        v = v > 0.f ? v : 0.2f * v;
        sum += __expf(v - mx);
    }
    red[t] = sum; __syncthreads();
#pragma unroll
    for (int off = 64; off >= 1; off >>= 1) {
        if (t < off) red[t] += red[t + off];
        __syncthreads();
    }
    const float sm = red[0];
    __syncthreads();

    float acc = 0.f;
    for (int c0 = 0; c0 < deg; c0 += 32) {
        int cn = min(32, deg - c0);
        if (t < cn) {
            int s = g_csrc[beg + c0 + t];
            s_srcs[t] = s;
            float v = g_als[s] + ald;
            v = v > 0.f ? v : 0.2f * v;
            s_alpha[t] = __expf(v - mx) / sm;
        }
        __syncthreads();
        for (int i = 0; i < cn; i++)
            acc = fmaf(hw[(size_t)s_srcs[i] * 128 + t], s_alpha[i], acc);
        __syncthreads();
    }
    out[(size_t)d * 128 + t] = acc + b[t];
}

// ---------------- fused pair-MLP scorer ------------------------------------
__global__ __launch_bounds__(128) void mlp_k(
    const float* __restrict__ h3, const int* __restrict__ liq,
    const int* __restrict__ ing,
    const float* __restrict__ mw1, const float* __restrict__ mb1,
    const float* __restrict__ mw2, const float* __restrict__ mb2,
    const float* __restrict__ mw3, const float* __restrict__ mb3,
    float* __restrict__ outp)
{
    __shared__ float pair[256];
    __shared__ float z1[128];
    __shared__ float z2[64];
    int row = blockIdx.x, t = threadIdx.x;
    int L = liq[row], I = ing[row];
    pair[t]       = h3[(size_t)L * 128 + t];
    pair[128 + t] = h3[(size_t)I * 128 + t];
    __syncthreads();
    float acc = mb1[t];
#pragma unroll 8
    for (int i = 0; i < 256; i++) acc = fmaf(pair[i], mw1[i * 128 + t], acc);
    z1[t] = fmaxf(acc, 0.f);
    __syncthreads();
    if (t < 64) {
        float a2 = mb2[t];
#pragma unroll 8
        for (int i = 0; i < 128; i++) a2 = fmaf(z1[i], mw2[i * 64 + t], a2);
        z2[t] = fmaxf(a2, 0.f);
    }
    __syncthreads();
    if (t < 32) {
        float a3 = fmaf(z2[t], mw3[t], z2[t + 32] * mw3[t + 32]);
#pragma unroll
        for (int o = 16; o; o >>= 1) a3 += __shfl_down_sync(0xffffffffu, a3, o);
        if (t == 0) outp[row] = 1.f / (1.f + expf(-(a3 + mb3[0])));
    }
}

extern "C" void kernel_launch(void* const* d_in, const int* in_sizes, int n_in,
                              void* d_out, int out_size)
{
    const float* x   = (const float*)d_in[0];
    const int*   ei  = (const int*)d_in[1];
    const int*   liq = (const int*)d_in[2];
    const int*   ing = (const int*)d_in[3];
    const float* W1  = (const float*)d_in[4];
    const float* as1 = (const float*)d_in[5];
    const float* ad1 = (const float*)d_in[6];
    const float* b1  = (const float*)d_in[7];
    const float* W2  = (const float*)d_in[8];
    const float* as2 = (const float*)d_in[9];
    const float* ad2 = (const float*)d_in[10];
    const float* b2  = (const float*)d_in[11];
    const float* W3  = (const float*)d_in[12];
    const float* as3 = (const float*)d_in[13];
    const float* ad3 = (const float*)d_in[14];
    const float* b3  = (const float*)d_in[15];
    const float* mw1 = (const float*)d_in[16];
    const float* mb1 = (const float*)d_in[17];
    const float* mw2 = (const float*)d_in[18];
    const float* mb2 = (const float*)d_in[19];
    const float* mw3 = (const float*)d_in[20];
    const float* mb3 = (const float*)d_in[21];
    float* outp = (float*)d_out;

    cudaFuncSetAttribute(mma_gemm_k,
                         cudaFuncAttributeMaxDynamicSharedMemorySize,
                         GEMM_SMEM_BYTES);

    float *hw, *bufC;
    __nv_bfloat16 *act, *xb, *wt1, *wt2, *wt3;
    cudaGetSymbolAddress((void**)&hw,   g_hw);
    cudaGetSymbolAddress((void**)&bufC, g_bufC);
    cudaGetSymbolAddress((void**)&act,  g_act);
    cudaGetSymbolAddress((void**)&xb,   g_xb);
    cudaGetSymbolAddress((void**)&wt1,  g_wt1);
    cudaGetSymbolAddress((void**)&wt2,  g_wt2);
    cudaGetSymbolAddress((void**)&wt3,  g_wt3);

    // conversions (independent of CSR build)
    cvt_x_k<<<(N_NODES * 64 + 255) / 256, 256>>>(x, N_NODES * 64);
    cvt_w_k<<<(64   * 1024 + 255) / 256, 256>>>(W1, wt1, 64,   1024);
    cvt_w_k<<<(1024 * 1024 + 255) / 256, 256>>>(W2, wt2, 1024, 1024);
    cvt_w_k<<<(1024 * 128  + 255) / 256, 256>>>(W3, wt3, 1024, 128);

    // CSR build
    build_zero_k<<<(E_TOT + 255) / 256, 256>>>(ei);
    hist_k<<<(E_TOT + 255) / 256, 256>>>();
    scan1_k<<<NBLK, 1024>>>();
    scan2_k<<<1, 32>>>();
    scan3_k<<<NBLK, 1024>>>();
    scatter_k<<<(E_TOT + 255) / 256, 256>>>();

    dim3 grid8(8, (N_NODES + 127) / 128);
    dim3 grid1(1, (N_NODES + 127) / 128);

    // layer 1: A = xb [M,64]
    mma_gemm_k<<<grid8, 256, GEMM_SMEM_BYTES>>>(xb, wt1, hw, N_NODES, 1024, 64,
                                                as1, ad1, 8);
    gat_fused8_k<<<N_NODES, 256>>>(hw, b1, act);

    // layer 2: A = act [M,1024]
    mma_gemm_k<<<grid8, 256, GEMM_SMEM_BYTES>>>(act, wt2, hw, N_NODES, 1024, 1024,
                                                as2, ad2, 8);
    gat_fused8_k<<<N_NODES, 256>>>(hw, b2, act);

    // layer 3: A = act [M,1024], N=128, H=1
    mma_gemm_k<<<grid1, 256, GEMM_SMEM_BYTES>>>(act, wt3, hw, N_NODES, 128, 1024,
                                                as3, ad3, 1);
    gat_fused1_k<<<N_NODES, 128>>>(hw, b3, bufC);

    mlp_k<<<4096, 128>>>(bufC, liq, ing, mw1, mb1, mw2, mb2, mw3, mb3, outp);
}

// round 6
// speedup vs baseline: 5.4745x; 1.1993x over previous
#include <cuda_runtime.h>
#include <cuda_bf16.h>
#include <math.h>
#include <stdint.h>

#define N_NODES 25000
#define N_EDGES 200000
#define E_TOT   (N_EDGES + N_NODES)
#define C_HID   128
#define F_BIG   1024
#define NBLK    ((N_NODES + 1023) / 1024)

// ---------------- device scratch -------------------------------------------
__device__ __nv_bfloat16  g_hw  [N_NODES * F_BIG];      // GEMM C (bf16)
__device__ __nv_bfloat16  g_act [N_NODES * F_BIG];      // activations (GEMM A)
__device__ __nv_bfloat16  g_xb  [N_NODES * 64];
__device__ __nv_bfloat16  g_wt1 [1024 * 64];
__device__ __nv_bfloat16  g_wt2 [1024 * 1024];
__device__ __nv_bfloat16  g_wt3 [128 * 1024];
__device__ float          g_bufC[N_NODES * C_HID];
__device__ float g_als [N_NODES * 8];
__device__ float g_ald [N_NODES * 8];
__device__ int   g_src [E_TOT];
__device__ int   g_dst [E_TOT];
__device__ int   g_rowptr[N_NODES + 1];
__device__ int   g_wptr  [N_NODES];
__device__ int   g_csrc  [E_TOT];
__device__ int   g_bsum  [NBLK];

// ---------------- cp.async helpers -----------------------------------------
__device__ __forceinline__ void cpa16(void* sdst, const void* gsrc, int sz) {
    uint32_t sa = (uint32_t)__cvta_generic_to_shared(sdst);
    asm volatile("cp.async.cg.shared.global [%0], [%1], 16, %2;"
                 :: "r"(sa), "l"(gsrc), "r"(sz) : "memory");
}
__device__ __forceinline__ void cpa_commit() {
    asm volatile("cp.async.commit_group;" ::: "memory");
}
template <int W> __device__ __forceinline__ void cpa_wait() {
    asm volatile("cp.async.wait_group %0;" :: "n"(W) : "memory");
}

// ---------------- conversions ----------------------------------------------
__global__ void cvt_x_k(const float* __restrict__ x, int n) {
    int i = blockIdx.x * blockDim.x + threadIdx.x;
    if (i < n) g_xb[i] = __float2bfloat16(x[i]);
}
__global__ void cvt_w_k(const float* __restrict__ W, __nv_bfloat16* __restrict__ Wt,
                        int K, int N) {
    int i = blockIdx.x * blockDim.x + threadIdx.x;
    if (i < K * N) {
        int k = i / N, n = i - k * N;
        Wt[(size_t)n * K + k] = __float2bfloat16(W[i]);
    }
}

// ---------------- edge list + CSR build ------------------------------------
__global__ void build_zero_k(const int* __restrict__ ei) {
    int i = blockIdx.x * blockDim.x + threadIdx.x;
    if (i < N_NODES) g_wptr[i] = 0;
    if (i < N_EDGES) {
        g_src[i] = ei[i];
        g_dst[i] = ei[N_EDGES + i];
    } else if (i < E_TOT) {
        int n = i - N_EDGES;
        g_src[i] = n;
        g_dst[i] = n;
    }
}
__global__ void hist_k() {
    int e = blockIdx.x * blockDim.x + threadIdx.x;
    if (e < E_TOT) atomicAdd(&g_wptr[g_dst[e]], 1);
}
__global__ __launch_bounds__(1024) void scan1_k() {
    __shared__ int ws[32];
    int t = threadIdx.x, lane = t & 31, wid = t >> 5;
    int idx = blockIdx.x * 1024 + t;
    int v = (idx < N_NODES) ? g_wptr[idx] : 0;
    int incl = v;
#pragma unroll
    for (int off = 1; off < 32; off <<= 1) {
        int y = __shfl_up_sync(0xffffffffu, incl, off);
        if (lane >= off) incl += y;
    }
    if (lane == 31) ws[wid] = incl;
    __syncthreads();
    if (wid == 0) {
        int s = ws[lane], si = s;
#pragma unroll
        for (int off = 1; off < 32; off <<= 1) {
            int y = __shfl_up_sync(0xffffffffu, si, off);
            if (lane >= off) si += y;
        }
        ws[lane] = si - s;
    }
    __syncthreads();
    int excl = incl - v + ws[wid];
    if (idx < N_NODES) g_rowptr[idx] = excl;
    if (t == 1023) g_bsum[blockIdx.x] = excl + v;
}
__global__ void scan2_k() {
    int lane = threadIdx.x;
    int v = (lane < NBLK) ? g_bsum[lane] : 0;
    int incl = v;
#pragma unroll
    for (int off = 1; off < 32; off <<= 1) {
        int y = __shfl_up_sync(0xffffffffu, incl, off);
        if (lane >= off) incl += y;
    }
    if (lane < NBLK) g_bsum[lane] = incl - v;
}
__global__ void scan3_k() {
    int idx = blockIdx.x * 1024 + threadIdx.x;
    if (idx < N_NODES) {
        int val = g_rowptr[idx] + g_bsum[blockIdx.x];
        g_rowptr[idx] = val;
        g_wptr[idx]   = val;
    }
    if (idx == 0) g_rowptr[N_NODES] = E_TOT;
}
__global__ void scatter_k() {
    int e = blockIdx.x * blockDim.x + threadIdx.x;
    if (e < E_TOT) {
        int pos = atomicAdd(&g_wptr[g_dst[e]], 1);
        g_csrc[pos] = g_src[e];
    }
}

// ---------------- bf16 tensor-core GEMM, fused attention dots --------------
// C[M,N] (bf16) = A[M,K] @ Wt[N,K]^T. CTA 128x128, BK=16, mma.m16n8k16.
#define GSTAGES 4
#define T_STRIDE 24
#define T_TILE   (128 * T_STRIDE)
#define GEMM_SMEM_BYTES (GSTAGES * 2 * T_TILE * 2)   // 49152 B

__global__ __launch_bounds__(256, 2) void mma_gemm_k(
    const __nv_bfloat16* __restrict__ A, const __nv_bfloat16* __restrict__ Bt,
    __nv_bfloat16* __restrict__ C, int M, int N, int K,
    const float* __restrict__ a_s, const float* __restrict__ a_d, int H)
{
    extern __shared__ __align__(16) __nv_bfloat16 smem_h[];
    __nv_bfloat16* As = smem_h;
    __nv_bfloat16* Bs = smem_h + GSTAGES * T_TILE;

    const int t    = threadIdx.x;
    const int bm   = blockIdx.y * 128;
    const int bn   = blockIdx.x * 128;
    const int head = blockIdx.x;
    const int warp = t >> 5, lane = t & 31;
    const int wm   = (warp >> 2) * 64;
    const int wn   = (warp & 3) * 32;
    const int gid  = lane >> 2;
    const int tg   = lane & 3;

    const int kTiles = K >> 4;

    const int srow = t >> 1;
    const int sch  = (t & 1) * 8;
    auto issue_tile = [&](int kt, int st) {
        __nv_bfloat16* as = As + st * T_TILE;
        __nv_bfloat16* bs = Bs + st * T_TILE;
        int grow = bm + srow;
        int sz = (grow < M) ? 16 : 0;
        if (grow >= M) grow = M - 1;
        cpa16(&as[srow * T_STRIDE + sch], A  + (size_t)grow * K + kt * 16 + sch, sz);
        cpa16(&bs[srow * T_STRIDE + sch], Bt + (size_t)(bn + srow) * K + kt * 16 + sch, 16);
    };

    float acc[4][4][4];
#pragma unroll
    for (int i = 0; i < 4; i++)
#pragma unroll
        for (int j = 0; j < 4; j++)
#pragma unroll
            for (int r = 0; r < 4; r++) acc[i][j][r] = 0.f;

#pragma unroll
    for (int s = 0; s < GSTAGES - 1; s++) {
        if (s < kTiles) issue_tile(s, s);
        cpa_commit();
    }

    for (int kt = 0; kt < kTiles; kt++) {
        cpa_wait<GSTAGES - 2>();
        __syncthreads();

        int nt = kt + GSTAGES - 1;
        if (nt < kTiles) issue_tile(nt, nt % GSTAGES);
        cpa_commit();

        const __nv_bfloat16* as = As + (kt % GSTAGES) * T_TILE;
        const __nv_bfloat16* bs = Bs + (kt % GSTAGES) * T_TILE;

        uint32_t af[4][4], bf[4][2];
#pragma unroll
        for (int mt = 0; mt < 4; mt++) {
            int r = wm + mt * 16 + gid;
            af[mt][0] = *(const uint32_t*)&as[(r)     * T_STRIDE + 2 * tg];
            af[mt][1] = *(const uint32_t*)&as[(r + 8) * T_STRIDE + 2 * tg];
            af[mt][2] = *(const uint32_t*)&as[(r)     * T_STRIDE + 2 * tg + 8];
            af[mt][3] = *(const uint32_t*)&as[(r + 8) * T_STRIDE + 2 * tg + 8];
        }
#pragma unroll
        for (int ntile = 0; ntile < 4; ntile++) {
            int c = wn + ntile * 8 + gid;
            bf[ntile][0] = *(const uint32_t*)&bs[c * T_STRIDE + 2 * tg];
            bf[ntile][1] = *(const uint32_t*)&bs[c * T_STRIDE + 2 * tg + 8];
        }
#pragma unroll
        for (int mt = 0; mt < 4; mt++) {
#pragma unroll
            for (int ntile = 0; ntile < 4; ntile++) {
                asm volatile(
                    "mma.sync.aligned.m16n8k16.row.col.f32.bf16.bf16.f32 "
                    "{%0,%1,%2,%3}, {%4,%5,%6,%7}, {%8,%9}, {%0,%1,%2,%3};\n"
                    : "+f"(acc[mt][ntile][0]), "+f"(acc[mt][ntile][1]),
                      "+f"(acc[mt][ntile][2]), "+f"(acc[mt][ntile][3])
                    : "r"(af[mt][0]), "r"(af[mt][1]), "r"(af[mt][2]), "r"(af[mt][3]),
                      "r"(bf[ntile][0]), "r"(bf[ntile][1]));
            }
        }
        __syncthreads();
    }

    // ---- epilogue 1: store C tile (bf16) ----
#pragma unroll
    for (int mt = 0; mt < 4; mt++) {
        int r0 = bm + wm + mt * 16 + gid;
#pragma unroll
        for (int ntile = 0; ntile < 4; ntile++) {
            int c = bn + wn + ntile * 8 + 2 * tg;
            if (r0 < M) {
                __nv_bfloat162 p =
                    __floats2bfloat162_rn(acc[mt][ntile][0], acc[mt][ntile][1]);
                *(uint32_t*)&C[(size_t)r0 * N + c] = *(uint32_t*)&p;
            }
            if (r0 + 8 < M) {
                __nv_bfloat162 p =
                    __floats2bfloat162_rn(acc[mt][ntile][2], acc[mt][ntile][3]);
                *(uint32_t*)&C[(size_t)(r0 + 8) * N + c] = *(uint32_t*)&p;
            }
        }
    }

    // ---- epilogue 2: fused attention dots (fp32 accumulators) ----
    float* s_red = (float*)smem_h;
    s_red[t] = 0.f;
    __syncthreads();

    const float* asv = a_s + head * 128;
    const float* adv = a_d + head * 128;
    float csa[8], cda[8];
#pragma unroll
    for (int ntile = 0; ntile < 4; ntile++) {
        int c = wn + ntile * 8 + 2 * tg;
        csa[ntile * 2]     = asv[c];
        csa[ntile * 2 + 1] = asv[c + 1];
        cda[ntile * 2]     = adv[c];
        cda[ntile * 2 + 1] = adv[c + 1];
    }
#pragma unroll
    for (int mt = 0; mt < 4; mt++) {
#pragma unroll
        for (int half = 0; half < 2; half++) {
            float rs = 0.f, rd = 0.f;
#pragma unroll
            for (int ntile = 0; ntile < 4; ntile++) {
                rs = fmaf(acc[mt][ntile][half * 2],     csa[ntile * 2],     rs);
                rs = fmaf(acc[mt][ntile][half * 2 + 1], csa[ntile * 2 + 1], rs);
                rd = fmaf(acc[mt][ntile][half * 2],     cda[ntile * 2],     rd);
                rd = fmaf(acc[mt][ntile][half * 2 + 1], cda[ntile * 2 + 1], rd);
            }
            rs += __shfl_xor_sync(0xffffffffu, rs, 1);
            rs += __shfl_xor_sync(0xffffffffu, rs, 2);
            rd += __shfl_xor_sync(0xffffffffu, rd, 1);
            rd += __shfl_xor_sync(0xffffffffu, rd, 2);
            if (tg == 0) {
                int rl = wm + mt * 16 + half * 8 + gid;
                atomicAdd(&s_red[rl * 2],     rs);
                atomicAdd(&s_red[rl * 2 + 1], rd);
            }
        }
    }
    __syncthreads();
    if (t < 128 && bm + t < M) {
        g_als[(bm + t) * H + head] = s_red[t * 2];
        g_ald[(bm + t) * H + head] = s_red[t * 2 + 1];
    }
}

// ---------------- fused GAT softmax + aggregation, H=8 ---------------------
// block per dst; warp w = head w for softmax stats (shfl reduce);
// channel phase: thread t owns channels 4t..4t+3 (bf16 uint2 gather).
__global__ __launch_bounds__(256) void gat_fused8_k(
    const __nv_bfloat16* __restrict__ hw, const float* __restrict__ b,
    __nv_bfloat16* __restrict__ act)
{
    __shared__ float s_max[8], s_sum[8], s_ald[8];
    __shared__ float s_alpha[32][8];
    __shared__ int   s_srcs[32];

    const int d = blockIdx.x;
    const int t = threadIdx.x;
    const int beg = g_rowptr[d], deg = g_rowptr[d + 1] - beg;
    const int w = t >> 5, lane = t & 31;
    const int h = t & 7, j = t >> 3;

    if (t < 8) s_ald[t] = g_ald[d * 8 + t];
    __syncwarp();

    // per-head softmax stats: warp w handles head w
    {
        const float ald = g_ald[d * 8 + w];
        float m = -INFINITY;
        for (int i = lane; i < deg; i += 32) {
            int s = g_csrc[beg + i];
            float v = g_als[s * 8 + w] + ald;
            v = v > 0.f ? v : 0.2f * v;
            m = fmaxf(m, v);
        }
#pragma unroll
        for (int o = 16; o; o >>= 1)
            m = fmaxf(m, __shfl_xor_sync(0xffffffffu, m, o));
        float sum = 0.f;
        for (int i = lane; i < deg; i += 32) {
            int s = g_csrc[beg + i];
            float v = g_als[s * 8 + w] + ald;
            v = v > 0.f ? v : 0.2f * v;
            sum += __expf(v - m);
        }
#pragma unroll
        for (int o = 16; o; o >>= 1)
            sum += __shfl_xor_sync(0xffffffffu, sum, o);
        if (lane == 0) { s_max[w] = m; s_sum[w] = sum; }
    }
    __syncthreads();

    const int hh = t >> 5;     // head of channels 4t..4t+3
    float4 a = make_float4(0.f, 0.f, 0.f, 0.f);
    for (int c0 = 0; c0 < deg; c0 += 32) {
        int cn = min(32, deg - c0);
        if (j < cn) {
            int s = g_csrc[beg + c0 + j];
            if (h == 0) s_srcs[j] = s;
            float v = g_als[s * 8 + h] + s_ald[h];
            v = v > 0.f ? v : 0.2f * v;
            s_alpha[j][h] = __expf(v - s_max[h]) / s_sum[h];
        }
        __syncthreads();
        for (int i = 0; i < cn; i++) {
            uint2 hv = *(const uint2*)(hw + (size_t)s_srcs[i] * 1024 + 4 * t);
            float2 f0 = __bfloat1622float2(*(__nv_bfloat162*)&hv.x);
            float2 f1 = __bfloat1622float2(*(__nv_bfloat162*)&hv.y);
            const float al = s_alpha[i][hh];
            a.x = fmaf(f0.x, al, a.x);
            a.y = fmaf(f0.y, al, a.y);
            a.z = fmaf(f1.x, al, a.z);
            a.w = fmaf(f1.y, al, a.w);
        }
        __syncthreads();
    }

    const float4 bv = ((const float4*)b)[t];
    a.x = fmaxf(a.x + bv.x, 0.f);
    a.y = fmaxf(a.y + bv.y, 0.f);
    a.z = fmaxf(a.z + bv.z, 0.f);
    a.w = fmaxf(a.w + bv.w, 0.f);
    __nv_bfloat162 p0 = __floats2bfloat162_rn(a.x, a.y);
    __nv_bfloat162 p1 = __floats2bfloat162_rn(a.z, a.w);
    uint2 packed = make_uint2(*(uint32_t*)&p0, *(uint32_t*)&p1);
    *(uint2*)&act[(size_t)d * 1024 + 4 * t] = packed;
}

// ---------------- fused GAT softmax + aggregation, H=1 (fp32 out) ----------
__global__ __launch_bounds__(128) void gat_fused1_k(
    const __nv_bfloat16* __restrict__ hw, const float* __restrict__ b,
    float* __restrict__ out)
{
    __shared__ float red[128];
    __shared__ float s_alpha[32];
    __shared__ int   s_srcs[32];

    const int d = blockIdx.x;
    const int t = threadIdx.x;
    const int beg = g_rowptr[d], deg = g_rowptr[d + 1] - beg;
    const float ald = g_ald[d];

    float m = -INFINITY;
    for (int i = t; i < deg; i += 128) {
        float v = g_als[g_csrc[beg + i]] + ald;
        v = v > 0.f ? v : 0.2f * v;
        m = fmaxf(m, v);
    }
    red[t] = m; __syncthreads();
#pragma unroll
    for (int off = 64; off >= 1; off >>= 1) {
        if (t < off) red[t] = fmaxf(red[t], red[t + off]);
        __syncthreads();
    }
    const float mx = red[0];
    __syncthreads();

    float sum = 0.f;
    for (int i = t; i < deg; i += 128) {
        float v = g_als[g_csrc[beg + i]] + ald;
        v = v > 0.f ? v : 0.2f * v;
        sum += __expf(v - mx);
    }
    red[t] = sum; __syncthreads();
#pragma unroll
    for (int off = 64; off >= 1; off >>= 1) {
        if (t < off) red[t] += red[t + off];
        __syncthreads();
    }
    const float sm = red[0];
    __syncthreads();

    float acc = 0.f;
    for (int c0 = 0; c0 < deg; c0 += 32) {
        int cn = min(32, deg - c0);
        if (t < cn) {
            int s = g_csrc[beg + c0 + t];
            s_srcs[t] = s;
            float v = g_als[s] + ald;
            v = v > 0.f ? v : 0.2f * v;
            s_alpha[t] = __expf(v - mx) / sm;
        }
        __syncthreads();
        for (int i = 0; i < cn; i++)
            acc = fmaf(__bfloat162float(hw[(size_t)s_srcs[i] * 128 + t]),
                       s_alpha[i], acc);
        __syncthreads();
    }
    out[(size_t)d * 128 + t] = acc + b[t];
}

// ---------------- fused pair-MLP scorer ------------------------------------
__global__ __launch_bounds__(128) void mlp_k(
    const float* __restrict__ h3, const int* __restrict__ liq,
    const int* __restrict__ ing,
    const float* __restrict__ mw1, const float* __restrict__ mb1,
    const float* __restrict__ mw2, const float* __restrict__ mb2,
    const float* __restrict__ mw3, const float* __restrict__ mb3,
    float* __restrict__ outp)
{
    __shared__ float pair[256];
    __shared__ float z1[128];
    __shared__ float z2[64];
    int row = blockIdx.x, t = threadIdx.x;
    int L = liq[row], I = ing[row];
    pair[t]       = h3[(size_t)L * 128 + t];
    pair[128 + t] = h3[(size_t)I * 128 + t];
    __syncthreads();
    float acc = mb1[t];
#pragma unroll 8
    for (int i = 0; i < 256; i++) acc = fmaf(pair[i], mw1[i * 128 + t], acc);
    z1[t] = fmaxf(acc, 0.f);
    __syncthreads();
    if (t < 64) {
        float a2 = mb2[t];
#pragma unroll 8
        for (int i = 0; i < 128; i++) a2 = fmaf(z1[i], mw2[i * 64 + t], a2);
        z2[t] = fmaxf(a2, 0.f);
    }
    __syncthreads();
    if (t < 32) {
        float a3 = fmaf(z2[t], mw3[t], z2[t + 32] * mw3[t + 32]);
#pragma unroll
        for (int o = 16; o; o >>= 1) a3 += __shfl_down_sync(0xffffffffu, a3, o);
        if (t == 0) outp[row] = 1.f / (1.f + expf(-(a3 + mb3[0])));
    }
}

extern "C" void kernel_launch(void* const* d_in, const int* in_sizes, int n_in,
                              void* d_out, int out_size)
{
    const float* x   = (const float*)d_in[0];
    const int*   ei  = (const int*)d_in[1];
    const int*   liq = (const int*)d_in[2];
    const int*   ing = (const int*)d_in[3];
    const float* W1  = (const float*)d_in[4];
    const float* as1 = (const float*)d_in[5];
    const float* ad1 = (const float*)d_in[6];
    const float* b1  = (const float*)d_in[7];
    const float* W2  = (const float*)d_in[8];
    const float* as2 = (const float*)d_in[9];
    const float* ad2 = (const float*)d_in[10];
    const float* b2  = (const float*)d_in[11];
    const float* W3  = (const float*)d_in[12];
    const float* as3 = (const float*)d_in[13];
    const float* ad3 = (const float*)d_in[14];
    const float* b3  = (const float*)d_in[15];
    const float* mw1 = (const float*)d_in[16];
    const float* mb1 = (const float*)d_in[17];
    const float* mw2 = (const float*)d_in[18];
    const float* mb2 = (const float*)d_in[19];
    const float* mw3 = (const float*)d_in[20];
    const float* mb3 = (const float*)d_in[21];
    float* outp = (float*)d_out;

    cudaFuncSetAttribute(mma_gemm_k,
                         cudaFuncAttributeMaxDynamicSharedMemorySize,
                         GEMM_SMEM_BYTES);

    float* bufC;
    __nv_bfloat16 *hw, *act, *xb, *wt1, *wt2, *wt3;
    cudaGetSymbolAddress((void**)&hw,   g_hw);
    cudaGetSymbolAddress((void**)&bufC, g_bufC);
    cudaGetSymbolAddress((void**)&act,  g_act);
    cudaGetSymbolAddress((void**)&xb,   g_xb);
    cudaGetSymbolAddress((void**)&wt1,  g_wt1);
    cudaGetSymbolAddress((void**)&wt2,  g_wt2);
    cudaGetSymbolAddress((void**)&wt3,  g_wt3);

    cvt_x_k<<<(N_NODES * 64 + 255) / 256, 256>>>(x, N_NODES * 64);
    cvt_w_k<<<(64   * 1024 + 255) / 256, 256>>>(W1, wt1, 64,   1024);
    cvt_w_k<<<(1024 * 1024 + 255) / 256, 256>>>(W2, wt2, 1024, 1024);
    cvt_w_k<<<(1024 * 128  + 255) / 256, 256>>>(W3, wt3, 1024, 128);

    build_zero_k<<<(E_TOT + 255) / 256, 256>>>(ei);
    hist_k<<<(E_TOT + 255) / 256, 256>>>();
    scan1_k<<<NBLK, 1024>>>();
    scan2_k<<<1, 32>>>();
    scan3_k<<<NBLK, 1024>>>();
    scatter_k<<<(E_TOT + 255) / 256, 256>>>();

    dim3 grid8(8, (N_NODES + 127) / 128);
    dim3 grid1(1, (N_NODES + 127) / 128);

    mma_gemm_k<<<grid8, 256, GEMM_SMEM_BYTES>>>(xb, wt1, hw, N_NODES, 1024, 64,
                                                as1, ad1, 8);
    gat_fused8_k<<<N_NODES, 256>>>(hw, b1, act);

    mma_gemm_k<<<grid8, 256, GEMM_SMEM_BYTES>>>(act, wt2, hw, N_NODES, 1024, 1024,
                                                as2, ad2, 8);
    gat_fused8_k<<<N_NODES, 256>>>(hw, b2, act);

    mma_gemm_k<<<grid1, 256, GEMM_SMEM_BYTES>>>(act, wt3, hw, N_NODES, 128, 1024,
                                                as3, ad3, 1);
    gat_fused1_k<<<N_NODES, 128>>>(hw, b3, bufC);

    mlp_k<<<4096, 128>>>(bufC, liq, ing, mw1, mb1, mw2, mb2, mw3, mb3, outp);
}

// round 7
// speedup vs baseline: 6.0493x; 1.1050x over previous
#include <cuda_runtime.h>
#include <cuda_bf16.h>
#include <math.h>
#include <stdint.h>

#define N_NODES 25000
#define N_EDGES 200000
#define E_TOT   (N_EDGES + N_NODES)
#define C_HID   128
#define F_BIG   1024
#define NBLK    ((N_NODES + 1023) / 1024)

// ---------------- device scratch -------------------------------------------
__device__ __nv_bfloat16  g_hw  [N_NODES * F_BIG];
__device__ __nv_bfloat16  g_act [N_NODES * F_BIG];
__device__ __nv_bfloat16  g_xb  [N_NODES * 64];
__device__ __nv_bfloat16  g_wt1 [1024 * 64];
__device__ __nv_bfloat16  g_wt2 [1024 * 1024];
__device__ __nv_bfloat16  g_wt3 [128 * 1024];
__device__ float          g_bufC[N_NODES * C_HID];
__device__ float g_als [N_NODES * 8];
__device__ float g_ald [N_NODES * 8];
__device__ int   g_src [E_TOT];
__device__ int   g_dst [E_TOT];
__device__ int   g_rowptr[N_NODES + 1];
__device__ int   g_wptr  [N_NODES];
__device__ int   g_csrc  [E_TOT];
__device__ int   g_bsum  [NBLK];

// ---------------- cp.async helpers -----------------------------------------
__device__ __forceinline__ void cpa16(void* sdst, const void* gsrc, int sz) {
    uint32_t sa = (uint32_t)__cvta_generic_to_shared(sdst);
    asm volatile("cp.async.cg.shared.global [%0], [%1], 16, %2;"
                 :: "r"(sa), "l"(gsrc), "r"(sz) : "memory");
}
__device__ __forceinline__ void cpa_commit() {
    asm volatile("cp.async.commit_group;" ::: "memory");
}
template <int W> __device__ __forceinline__ void cpa_wait() {
    asm volatile("cp.async.wait_group %0;" :: "n"(W) : "memory");
}
__device__ __forceinline__ void ldsm_x4(uint32_t& r0, uint32_t& r1,
                                        uint32_t& r2, uint32_t& r3, uint32_t a) {
    asm volatile("ldmatrix.sync.aligned.m8n8.x4.shared.b16 {%0,%1,%2,%3}, [%4];"
                 : "=r"(r0), "=r"(r1), "=r"(r2), "=r"(r3) : "r"(a));
}

// ---------------- fused conversions ----------------------------------------
#define SEG0 (N_NODES * 64)          // x -> xb
#define SEG1 (SEG0 + 64 * 1024)      // W1 -> wt1
#define SEG2 (SEG1 + 1024 * 1024)    // W2 -> wt2
#define SEG3 (SEG2 + 1024 * 128)     // W3 -> wt3
__global__ void cvt_all_k(const float* __restrict__ x,
                          const float* __restrict__ W1,
                          const float* __restrict__ W2,
                          const float* __restrict__ W3) {
    int i = blockIdx.x * blockDim.x + threadIdx.x;
    if (i < SEG0) {
        g_xb[i] = __float2bfloat16(x[i]);
    } else if (i < SEG1) {
        int j = i - SEG0;  int k = j >> 10, n = j & 1023;
        g_wt1[(size_t)n * 64 + k] = __float2bfloat16(W1[j]);
    } else if (i < SEG2) {
        int j = i - SEG1;  int k = j >> 10, n = j & 1023;
        g_wt2[(size_t)n * 1024 + k] = __float2bfloat16(W2[j]);
    } else if (i < SEG3) {
        int j = i - SEG2;  int k = j >> 7, n = j & 127;
        g_wt3[(size_t)n * 1024 + k] = __float2bfloat16(W3[j]);
    }
}

// ---------------- edge list + CSR build ------------------------------------
__global__ void build_zero_k(const int* __restrict__ ei) {
    int i = blockIdx.x * blockDim.x + threadIdx.x;
    if (i < N_NODES) g_wptr[i] = 0;
    if (i < N_EDGES) {
        g_src[i] = ei[i];
        g_dst[i] = ei[N_EDGES + i];
    } else if (i < E_TOT) {
        int n = i - N_EDGES;
        g_src[i] = n;
        g_dst[i] = n;
    }
}
__global__ void hist_k() {
    int e = blockIdx.x * blockDim.x + threadIdx.x;
    if (e < E_TOT) atomicAdd(&g_wptr[g_dst[e]], 1);
}
__global__ __launch_bounds__(1024) void scan1_k() {
    __shared__ int ws[32];
    int t = threadIdx.x, lane = t & 31, wid = t >> 5;
    int idx = blockIdx.x * 1024 + t;
    int v = (idx < N_NODES) ? g_wptr[idx] : 0;
    int incl = v;
#pragma unroll
    for (int off = 1; off < 32; off <<= 1) {
        int y = __shfl_up_sync(0xffffffffu, incl, off);
        if (lane >= off) incl += y;
    }
    if (lane == 31) ws[wid] = incl;
    __syncthreads();
    if (wid == 0) {
        int s = ws[lane], si = s;
#pragma unroll
        for (int off = 1; off < 32; off <<= 1) {
            int y = __shfl_up_sync(0xffffffffu, si, off);
            if (lane >= off) si += y;
        }
        ws[lane] = si - s;
    }
    __syncthreads();
    int excl = incl - v + ws[wid];
    if (idx < N_NODES) g_rowptr[idx] = excl;
    if (t == 1023) g_bsum[blockIdx.x] = excl + v;
}
__global__ void scan2_k() {
    int lane = threadIdx.x;
    int v = (lane < NBLK) ? g_bsum[lane] : 0;
    int incl = v;
#pragma unroll
    for (int off = 1; off < 32; off <<= 1) {
        int y = __shfl_up_sync(0xffffffffu, incl, off);
        if (lane >= off) incl += y;
    }
    if (lane < NBLK) g_bsum[lane] = incl - v;
}
__global__ void scan3_k() {
    int idx = blockIdx.x * 1024 + threadIdx.x;
    if (idx < N_NODES) {
        int val = g_rowptr[idx] + g_bsum[blockIdx.x];
        g_rowptr[idx] = val;
        g_wptr[idx]   = val;
    }
    if (idx == 0) g_rowptr[N_NODES] = E_TOT;
}
__global__ void scatter_k() {
    int e = blockIdx.x * blockDim.x + threadIdx.x;
    if (e < E_TOT) {
        int pos = atomicAdd(&g_wptr[g_dst[e]], 1);
        g_csrc[pos] = g_src[e];
    }
}

// ---------------- bf16 tensor-core GEMM (ldmatrix), fused att-dots ---------
#define GSTAGES 4
#define T_STRIDE 24
#define T_TILE   (128 * T_STRIDE)
#define STAGE_BYTES (T_TILE * 2)
#define GEMM_SMEM_BYTES (GSTAGES * 2 * STAGE_BYTES)   // 49152 B

__global__ __launch_bounds__(256, 2) void mma_gemm_k(
    const __nv_bfloat16* __restrict__ A, const __nv_bfloat16* __restrict__ Bt,
    __nv_bfloat16* __restrict__ C, int M, int N, int K,
    const float* __restrict__ a_s, const float* __restrict__ a_d, int H)
{
    extern __shared__ __align__(16) __nv_bfloat16 smem_h[];
    __nv_bfloat16* As = smem_h;
    __nv_bfloat16* Bs = smem_h + GSTAGES * T_TILE;

    const int t    = threadIdx.x;
    const int bm   = blockIdx.y * 128;
    const int bn   = blockIdx.x * 128;
    const int head = blockIdx.x;
    const int warp = t >> 5, lane = t & 31;
    const int wm   = (warp >> 2) * 64;
    const int wn   = (warp & 3) * 32;
    const int gid  = lane >> 2;
    const int tg   = lane & 3;

    const int kTiles = K >> 4;

    const int srow = t >> 1;
    const int sch  = (t & 1) * 8;
    auto issue_tile = [&](int kt, int st) {
        __nv_bfloat16* as = As + st * T_TILE;
        __nv_bfloat16* bs = Bs + st * T_TILE;
        int grow = bm + srow;
        int sz = (grow < M) ? 16 : 0;
        if (grow >= M) grow = M - 1;
        cpa16(&as[srow * T_STRIDE + sch], A  + (size_t)grow * K + kt * 16 + sch, sz);
        cpa16(&bs[srow * T_STRIDE + sch], Bt + (size_t)(bn + srow) * K + kt * 16 + sch, 16);
    };

    // ---- precomputed ldmatrix lane addresses (stage 0) ----
    // quad q = lane>>3, r = lane&7
    const int q = lane >> 3, r = lane & 7;
    const uint32_t as0 = (uint32_t)__cvta_generic_to_shared(As);
    const uint32_t bs0 = (uint32_t)__cvta_generic_to_shared(Bs);
    uint32_t a_addr[4], b_addr[2];
#pragma unroll
    for (int mt = 0; mt < 4; mt++) {
        int row = wm + mt * 16 + r + ((q & 1) << 3);
        int col = (q >> 1) << 3;
        a_addr[mt] = as0 + (row * T_STRIDE + col) * 2;
    }
#pragma unroll
    for (int p = 0; p < 2; p++) {
        int row = wn + ((p * 2 + (q >> 1)) << 3) + r;
        int col = (q & 1) << 3;
        b_addr[p] = bs0 + (row * T_STRIDE + col) * 2;
    }

    float acc[4][4][4];
#pragma unroll
    for (int i = 0; i < 4; i++)
#pragma unroll
        for (int j = 0; j < 4; j++)
#pragma unroll
            for (int z = 0; z < 4; z++) acc[i][j][z] = 0.f;

#pragma unroll
    for (int s = 0; s < GSTAGES - 1; s++) {
        if (s < kTiles) issue_tile(s, s);
        cpa_commit();
    }

    for (int kt = 0; kt < kTiles; kt++) {
        cpa_wait<GSTAGES - 2>();
        __syncthreads();

        int nt = kt + GSTAGES - 1;
        if (nt < kTiles) issue_tile(nt, nt % GSTAGES);
        cpa_commit();

        const uint32_t soff = (uint32_t)((kt % GSTAGES) * STAGE_BYTES);

        uint32_t af[4][4], bf[4][2];
#pragma unroll
        for (int mt = 0; mt < 4; mt++)
            ldsm_x4(af[mt][0], af[mt][1], af[mt][2], af[mt][3], a_addr[mt] + soff);
#pragma unroll
        for (int p = 0; p < 2; p++)
            ldsm_x4(bf[p * 2][0], bf[p * 2][1], bf[p * 2 + 1][0], bf[p * 2 + 1][1],
                    b_addr[p] + soff);

#pragma unroll
        for (int mt = 0; mt < 4; mt++) {
#pragma unroll
            for (int ntile = 0; ntile < 4; ntile++) {
                asm volatile(
                    "mma.sync.aligned.m16n8k16.row.col.f32.bf16.bf16.f32 "
                    "{%0,%1,%2,%3}, {%4,%5,%6,%7}, {%8,%9}, {%0,%1,%2,%3};\n"
                    : "+f"(acc[mt][ntile][0]), "+f"(acc[mt][ntile][1]),
                      "+f"(acc[mt][ntile][2]), "+f"(acc[mt][ntile][3])
                    : "r"(af[mt][0]), "r"(af[mt][1]), "r"(af[mt][2]), "r"(af[mt][3]),
                      "r"(bf[ntile][0]), "r"(bf[ntile][1]));
            }
        }
        __syncthreads();
    }

    // ---- epilogue 1: store C tile (bf16) ----
#pragma unroll
    for (int mt = 0; mt < 4; mt++) {
        int r0 = bm + wm + mt * 16 + gid;
#pragma unroll
        for (int ntile = 0; ntile < 4; ntile++) {
            int c = bn + wn + ntile * 8 + 2 * tg;
            if (r0 < M) {
                __nv_bfloat162 p =
                    __floats2bfloat162_rn(acc[mt][ntile][0], acc[mt][ntile][1]);
                *(uint32_t*)&C[(size_t)r0 * N + c] = *(uint32_t*)&p;
            }
            if (r0 + 8 < M) {
                __nv_bfloat162 p =
                    __floats2bfloat162_rn(acc[mt][ntile][2], acc[mt][ntile][3]);
                *(uint32_t*)&C[(size_t)(r0 + 8) * N + c] = *(uint32_t*)&p;
            }
        }
    }

    // ---- epilogue 2: fused attention dots ----
    float* s_red = (float*)smem_h;
    s_red[t] = 0.f;
    __syncthreads();

    const float* asv = a_s + head * 128;
    const float* adv = a_d + head * 128;
    float csa[8], cda[8];
#pragma unroll
    for (int ntile = 0; ntile < 4; ntile++) {
        int c = wn + ntile * 8 + 2 * tg;
        csa[ntile * 2]     = asv[c];
        csa[ntile * 2 + 1] = asv[c + 1];
        cda[ntile * 2]     = adv[c];
        cda[ntile * 2 + 1] = adv[c + 1];
    }
#pragma unroll
    for (int mt = 0; mt < 4; mt++) {
#pragma unroll
        for (int half = 0; half < 2; half++) {
            float rs = 0.f, rd = 0.f;
#pragma unroll
            for (int ntile = 0; ntile < 4; ntile++) {
                rs = fmaf(acc[mt][ntile][half * 2],     csa[ntile * 2],     rs);
                rs = fmaf(acc[mt][ntile][half * 2 + 1], csa[ntile * 2 + 1], rs);
                rd = fmaf(acc[mt][ntile][half * 2],     cda[ntile * 2],     rd);
                rd = fmaf(acc[mt][ntile][half * 2 + 1], cda[ntile * 2 + 1], rd);
            }
            rs += __shfl_xor_sync(0xffffffffu, rs, 1);
            rs += __shfl_xor_sync(0xffffffffu, rs, 2);
            rd += __shfl_xor_sync(0xffffffffu, rd, 1);
            rd += __shfl_xor_sync(0xffffffffu, rd, 2);
            if (tg == 0) {
                int rl = wm + mt * 16 + half * 8 + gid;
                atomicAdd(&s_red[rl * 2],     rs);
                atomicAdd(&s_red[rl * 2 + 1], rd);
            }
        }
    }
    __syncthreads();
    if (t < 128 && bm + t < M) {
        g_als[(bm + t) * H + head] = s_red[t * 2];
        g_ald[(bm + t) * H + head] = s_red[t * 2 + 1];
    }
}

// ---------------- fused GAT softmax + aggregation, H=8 ---------------------
__global__ __launch_bounds__(256) void gat_fused8_k(
    const __nv_bfloat16* __restrict__ hw, const float* __restrict__ b,
    __nv_bfloat16* __restrict__ act)
{
    __shared__ float s_max[8], s_sum[8], s_ald[8];
    __shared__ float s_alpha[32][8];
    __shared__ int   s_srcs[32];

    const int d = blockIdx.x;
    const int t = threadIdx.x;
    const int beg = g_rowptr[d], deg = g_rowptr[d + 1] - beg;
    const int w = t >> 5, lane = t & 31;
    const int h = t & 7, j = t >> 3;

    if (t < 8) s_ald[t] = g_ald[d * 8 + t];

    {
        const float ald = g_ald[d * 8 + w];
        float m = -INFINITY;
        for (int i = lane; i < deg; i += 32) {
            int s = g_csrc[beg + i];
            float v = g_als[s * 8 + w] + ald;
            v = v > 0.f ? v : 0.2f * v;
            m = fmaxf(m, v);
        }
#pragma unroll
        for (int o = 16; o; o >>= 1)
            m = fmaxf(m, __shfl_xor_sync(0xffffffffu, m, o));
        float sum = 0.f;
        for (int i = lane; i < deg; i += 32) {
            int s = g_csrc[beg + i];
            float v = g_als[s * 8 + w] + ald;
            v = v > 0.f ? v : 0.2f * v;
            sum += __expf(v - m);
        }
#pragma unroll
        for (int o = 16; o; o >>= 1)
            sum += __shfl_xor_sync(0xffffffffu, sum, o);
        if (lane == 0) { s_max[w] = m; s_sum[w] = sum; }
    }
    __syncthreads();

    const int hh = t >> 5;
    float4 a = make_float4(0.f, 0.f, 0.f, 0.f);
    for (int c0 = 0; c0 < deg; c0 += 32) {
        int cn = min(32, deg - c0);
        if (j < cn) {
            int s = g_csrc[beg + c0 + j];
            if (h == 0) s_srcs[j] = s;
            float v = g_als[s * 8 + h] + s_ald[h];
            v = v > 0.f ? v : 0.2f * v;
            s_alpha[j][h] = __expf(v - s_max[h]) / s_sum[h];
        }
        __syncthreads();
        for (int i = 0; i < cn; i++) {
            uint2 hv = *(const uint2*)(hw + (size_t)s_srcs[i] * 1024 + 4 * t);
            float2 f0 = __bfloat1622float2(*(__nv_bfloat162*)&hv.x);
            float2 f1 = __bfloat1622float2(*(__nv_bfloat162*)&hv.y);
            const float al = s_alpha[i][hh];
            a.x = fmaf(f0.x, al, a.x);
            a.y = fmaf(f0.y, al, a.y);
            a.z = fmaf(f1.x, al, a.z);
            a.w = fmaf(f1.y, al, a.w);
        }
        __syncthreads();
    }

    const float4 bv = ((const float4*)b)[t];
    a.x = fmaxf(a.x + bv.x, 0.f);
    a.y = fmaxf(a.y + bv.y, 0.f);
    a.z = fmaxf(a.z + bv.z, 0.f);
    a.w = fmaxf(a.w + bv.w, 0.f);
    __nv_bfloat162 p0 = __floats2bfloat162_rn(a.x, a.y);
    __nv_bfloat162 p1 = __floats2bfloat162_rn(a.z, a.w);
    uint2 packed = make_uint2(*(uint32_t*)&p0, *(uint32_t*)&p1);
    *(uint2*)&act[(size_t)d * 1024 + 4 * t] = packed;
}

// ---------------- fused GAT softmax + aggregation, H=1 (fp32 out) ----------
__global__ __launch_bounds__(128) void gat_fused1_k(
    const __nv_bfloat16* __restrict__ hw, const float* __restrict__ b,
    float* __restrict__ out)
{
    __shared__ float red[128];
    __shared__ float s_alpha[32];
    __shared__ int   s_srcs[32];

    const int d = blockIdx.x;
    const int t = threadIdx.x;
    const int beg = g_rowptr[d], deg = g_rowptr[d + 1] - beg;
    const float ald = g_ald[d];

    float m = -INFINITY;
    for (int i = t; i < deg; i += 128) {
        float v = g_als[g_csrc[beg + i]] + ald;
        v = v > 0.f ? v : 0.2f * v;
        m = fmaxf(m, v);
    }
    red[t] = m; __syncthreads();
#pragma unroll
    for (int off = 64; off >= 1; off >>= 1) {
        if (t < off) red[t] = fmaxf(red[t], red[t + off]);
        __syncthreads();
    }
    const float mx = red[0];
    __syncthreads();

    float sum = 0.f;
    for (int i = t; i < deg; i += 128) {
        float v = g_als[g_csrc[beg + i]] + ald;
        v = v > 0.f ? v : 0.2f * v;
        sum += __expf(v - mx);
    }
    red[t] = sum; __syncthreads();
#pragma unroll
    for (int off = 64; off >= 1; off >>= 1) {
        if (t < off) red[t] += red[t + off];
        __syncthreads();
    }
    const float sm = red[0];
    __syncthreads();

    float acc = 0.f;
    for (int c0 = 0; c0 < deg; c0 += 32) {
        int cn = min(32, deg - c0);
        if (t < cn) {
            int s = g_csrc[beg + c0 + t];
            s_srcs[t] = s;
            float v = g_als[s] + ald;
            v = v > 0.f ? v : 0.2f * v;
            s_alpha[t] = __expf(v - mx) / sm;
        }
        __syncthreads();
        for (int i = 0; i < cn; i++)
            acc = fmaf(__bfloat162float(hw[(size_t)s_srcs[i] * 128 + t]),
                       s_alpha[i], acc);
        __syncthreads();
    }
    out[(size_t)d * 128 + t] = acc + b[t];
}

// ---------------- fused pair-MLP scorer ------------------------------------
__global__ __launch_bounds__(128) void mlp_k(
    const float* __restrict__ h3, const int* __restrict__ liq,
    const int* __restrict__ ing,
    const float* __restrict__ mw1, const float* __restrict__ mb1,
    const float* __restrict__ mw2, const float* __restrict__ mb2,
    const float* __restrict__ mw3, const float* __restrict__ mb3,
    float* __restrict__ outp)
{
    __shared__ float pair[256];
    __shared__ float z1[128];
    __shared__ float z2[64];
    int row = blockIdx.x, t = threadIdx.x;
    int L = liq[row], I = ing[row];
    pair[t]       = h3[(size_t)L * 128 + t];
    pair[128 + t] = h3[(size_t)I * 128 + t];
    __syncthreads();
    float acc = mb1[t];
#pragma unroll 8
    for (int i = 0; i < 256; i++) acc = fmaf(pair[i], mw1[i * 128 + t], acc);
    z1[t] = fmaxf(acc, 0.f);
    __syncthreads();
    if (t < 64) {
        float a2 = mb2[t];
#pragma unroll 8
        for (int i = 0; i < 128; i++) a2 = fmaf(z1[i], mw2[i * 64 + t], a2);
        z2[t] = fmaxf(a2, 0.f);
    }
    __syncthreads();
    if (t < 32) {
        float a3 = fmaf(z2[t], mw3[t], z2[t + 32] * mw3[t + 32]);
#pragma unroll
        for (int o = 16; o; o >>= 1) a3 += __shfl_down_sync(0xffffffffu, a3, o);
        if (t == 0) outp[row] = 1.f / (1.f + expf(-(a3 + mb3[0])));
    }
}

extern "C" void kernel_launch(void* const* d_in, const int* in_sizes, int n_in,
                              void* d_out, int out_size)
{
    const float* x   = (const float*)d_in[0];
    const int*   ei  = (const int*)d_in[1];
    const int*   liq = (const int*)d_in[2];
    const int*   ing = (const int*)d_in[3];
    const float* W1  = (const float*)d_in[4];
    const float* as1 = (const float*)d_in[5];
    const float* ad1 = (const float*)d_in[6];
    const float* b1  = (const float*)d_in[7];
    const float* W2  = (const float*)d_in[8];
    const float* as2 = (const float*)d_in[9];
    const float* ad2 = (const float*)d_in[10];
    const float* b2  = (const float*)d_in[11];
    const float* W3  = (const float*)d_in[12];
    const float* as3 = (const float*)d_in[13];
    const float* ad3 = (const float*)d_in[14];
    const float* b3  = (const float*)d_in[15];
    const float* mw1 = (const float*)d_in[16];
    const float* mb1 = (const float*)d_in[17];
    const float* mw2 = (const float*)d_in[18];
    const float* mb2 = (const float*)d_in[19];
    const float* mw3 = (const float*)d_in[20];
    const float* mb3 = (const float*)d_in[21];
    float* outp = (float*)d_out;

    cudaFuncSetAttribute(mma_gemm_k,
                         cudaFuncAttributeMaxDynamicSharedMemorySize,
                         GEMM_SMEM_BYTES);

    float* bufC;
    __nv_bfloat16 *hw, *act, *xb, *wt1, *wt2, *wt3;
    cudaGetSymbolAddress((void**)&hw,   g_hw);
    cudaGetSymbolAddress((void**)&bufC, g_bufC);
    cudaGetSymbolAddress((void**)&act,  g_act);
    cudaGetSymbolAddress((void**)&xb,   g_xb);
    cudaGetSymbolAddress((void**)&wt1,  g_wt1);
    cudaGetSymbolAddress((void**)&wt2,  g_wt2);
    cudaGetSymbolAddress((void**)&wt3,  g_wt3);

    cvt_all_k<<<(SEG3 + 255) / 256, 256>>>(x, W1, W2, W3);

    build_zero_k<<<(E_TOT + 255) / 256, 256>>>(ei);
    hist_k<<<(E_TOT + 255) / 256, 256>>>();
    scan1_k<<<NBLK, 1024>>>();
    scan2_k<<<1, 32>>>();
    scan3_k<<<NBLK, 1024>>>();
    scatter_k<<<(E_TOT + 255) / 256, 256>>>();

    dim3 grid8(8, (N_NODES + 127) / 128);
    dim3 grid1(1, (N_NODES + 127) / 128);

    mma_gemm_k<<<grid8, 256, GEMM_SMEM_BYTES>>>(xb, wt1, hw, N_NODES, 1024, 64,
                                                as1, ad1, 8);
    gat_fused8_k<<<N_NODES, 256>>>(hw, b1, act);

    mma_gemm_k<<<grid8, 256, GEMM_SMEM_BYTES>>>(act, wt2, hw, N_NODES, 1024, 1024,
                                                as2, ad2, 8);
    gat_fused8_k<<<N_NODES, 256>>>(hw, b2, act);

    mma_gemm_k<<<grid1, 256, GEMM_SMEM_BYTES>>>(act, wt3, hw, N_NODES, 128, 1024,
                                                as3, ad3, 1);
    gat_fused1_k<<<N_NODES, 128>>>(hw, b3, bufC);

    mlp_k<<<4096, 128>>>(bufC, liq, ing, mw1, mb1, mw2, mb2, mw3, mb3, outp);
}

// round 9
// speedup vs baseline: 6.0712x; 1.0036x over previous
#include <cuda_runtime.h>
#include <cuda_bf16.h>
#include <math.h>
#include <stdint.h>

#define N_NODES 25000
#define N_EDGES 200000
#define E_TOT   (N_EDGES + N_NODES)
#define C_HID   128
#define F_BIG   1024
#define NBLK    ((N_NODES + 1023) / 1024)

// ---------------- device scratch -------------------------------------------
__device__ __nv_bfloat16  g_hw  [N_NODES * F_BIG];
__device__ __nv_bfloat16  g_act [N_NODES * F_BIG];
__device__ __nv_bfloat16  g_xb  [N_NODES * 64];
__device__ __nv_bfloat16  g_wt1 [1024 * 64];
__device__ __nv_bfloat16  g_wt2 [1024 * 1024];
__device__ __nv_bfloat16  g_wt3 [128 * 1024];
__device__ float          g_bufC[N_NODES * C_HID];
__device__ float g_als [N_NODES * 8];
__device__ float g_ald [N_NODES * 8];
__device__ int   g_src [E_TOT];
__device__ int   g_dst [E_TOT];
__device__ int   g_rowptr[N_NODES + 1];
__device__ int   g_wptr  [N_NODES];
__device__ int   g_csrc  [E_TOT];
__device__ int   g_bsum  [NBLK];

// ---------------- cp.async helpers -----------------------------------------
__device__ __forceinline__ void cpa16(void* sdst, const void* gsrc, int sz) {
    uint32_t sa = (uint32_t)__cvta_generic_to_shared(sdst);
    asm volatile("cp.async.cg.shared.global [%0], [%1], 16, %2;"
                 :: "r"(sa), "l"(gsrc), "r"(sz) : "memory");
}
__device__ __forceinline__ void cpa_commit() {
    asm volatile("cp.async.commit_group;" ::: "memory");
}
template <int W> __device__ __forceinline__ void cpa_wait() {
    asm volatile("cp.async.wait_group %0;" :: "n"(W) : "memory");
}
__device__ __forceinline__ void ldsm_x4(uint32_t& r0, uint32_t& r1,
                                        uint32_t& r2, uint32_t& r3, uint32_t a) {
    asm volatile("ldmatrix.sync.aligned.m8n8.x4.shared.b16 {%0,%1,%2,%3}, [%4];"
                 : "=r"(r0), "=r"(r1), "=r"(r2), "=r"(r3) : "r"(a));
}

// ---------------- fused conversions (+ wptr zeroing) ------------------------
#define SEG0 (N_NODES * 64)
#define SEG1 (SEG0 + 64 * 1024)
#define SEG2 (SEG1 + 1024 * 1024)
#define SEG3 (SEG2 + 1024 * 128)
__global__ void cvt_all_k(const float* __restrict__ x,
                          const float* __restrict__ W1,
                          const float* __restrict__ W2,
                          const float* __restrict__ W3) {
    int i = blockIdx.x * blockDim.x + threadIdx.x;
    if (i < N_NODES) g_wptr[i] = 0;
    if (i < SEG0) {
        g_xb[i] = __float2bfloat16(x[i]);
    } else if (i < SEG1) {
        int j = i - SEG0;  int k = j >> 10, n = j & 1023;
        g_wt1[(size_t)n * 64 + k] = __float2bfloat16(W1[j]);
    } else if (i < SEG2) {
        int j = i - SEG1;  int k = j >> 10, n = j & 1023;
        g_wt2[(size_t)n * 1024 + k] = __float2bfloat16(W2[j]);
    } else if (i < SEG3) {
        int j = i - SEG2;  int k = j >> 7, n = j & 127;
        g_wt3[(size_t)n * 1024 + k] = __float2bfloat16(W3[j]);
    }
}

// ---------------- edge build + histogram (fused) ----------------------------
__global__ void build_hist_k(const int* __restrict__ ei) {
    int i = blockIdx.x * blockDim.x + threadIdx.x;
    if (i < N_EDGES) {
        int s = ei[i], d = ei[N_EDGES + i];
        g_src[i] = s;
        g_dst[i] = d;
        atomicAdd(&g_wptr[d], 1);
    } else if (i < E_TOT) {
        int n = i - N_EDGES;
        g_src[i] = n;
        g_dst[i] = n;
        atomicAdd(&g_wptr[n], 1);
    }
}
__global__ __launch_bounds__(1024) void scan1_k() {
    __shared__ int ws[32];
    int t = threadIdx.x, lane = t & 31, wid = t >> 5;
    int idx = blockIdx.x * 1024 + t;
    int v = (idx < N_NODES) ? g_wptr[idx] : 0;
    int incl = v;
#pragma unroll
    for (int off = 1; off < 32; off <<= 1) {
        int y = __shfl_up_sync(0xffffffffu, incl, off);
        if (lane >= off) incl += y;
    }
    if (lane == 31) ws[wid] = incl;
    __syncthreads();
    if (wid == 0) {
        int s = ws[lane], si = s;
#pragma unroll
        for (int off = 1; off < 32; off <<= 1) {
            int y = __shfl_up_sync(0xffffffffu, si, off);
            if (lane >= off) si += y;
        }
        ws[lane] = si - s;
    }
    __syncthreads();
    int excl = incl - v + ws[wid];
    if (idx < N_NODES) g_rowptr[idx] = excl;
    if (t == 1023) g_bsum[blockIdx.x] = excl + v;
}
__global__ void scan2_k() {
    int lane = threadIdx.x;
    int v = (lane < NBLK) ? g_bsum[lane] : 0;
    int incl = v;
#pragma unroll
    for (int off = 1; off < 32; off <<= 1) {
        int y = __shfl_up_sync(0xffffffffu, incl, off);
        if (lane >= off) incl += y;
    }
    if (lane < NBLK) g_bsum[lane] = incl - v;
}
__global__ void scan3_k() {
    int idx = blockIdx.x * 1024 + threadIdx.x;
    if (idx < N_NODES) {
        int val = g_rowptr[idx] + g_bsum[blockIdx.x];
        g_rowptr[idx] = val;
        g_wptr[idx]   = val;
    }
    if (idx == 0) g_rowptr[N_NODES] = E_TOT;
}
__global__ void scatter_k() {
    int e = blockIdx.x * blockDim.x + threadIdx.x;
    if (e < E_TOT) {
        int pos = atomicAdd(&g_wptr[g_dst[e]], 1);
        g_csrc[pos] = g_src[e];
    }
}

// ---------------- bf16 tensor-core GEMM (ldmatrix, BK=32), fused att-dots --
#define GSTAGES 4
#define T_STRIDE 40
#define T_TILE   (128 * T_STRIDE)
#define STAGE_BYTES (T_TILE * 2)                       // 10240 B
#define GEMM_SMEM_BYTES (GSTAGES * 2 * STAGE_BYTES)    // 81920 B

__global__ __launch_bounds__(256, 2) void mma_gemm_k(
    const __nv_bfloat16* __restrict__ A, const __nv_bfloat16* __restrict__ Bt,
    __nv_bfloat16* __restrict__ C, int M, int N, int K,
    const float* __restrict__ a_s, const float* __restrict__ a_d, int H)
{
    extern __shared__ __align__(16) __nv_bfloat16 smem_h[];
    __nv_bfloat16* As = smem_h;
    __nv_bfloat16* Bs = smem_h + GSTAGES * T_TILE;

    const int t    = threadIdx.x;
    const int bm   = blockIdx.y * 128;
    const int bn   = blockIdx.x * 128;
    const int head = blockIdx.x;
    const int warp = t >> 5, lane = t & 31;
    const int wm   = (warp >> 2) * 64;
    const int wn   = (warp & 3) * 32;
    const int gid  = lane >> 2;
    const int tg   = lane & 3;

    const int kTiles = K >> 5;     // BK = 32

    // staging: per 32-k tile each of A,B = 128 rows x 64 B = 512 x 16B chunks
    auto issue_tile = [&](int kt, int st) {
        __nv_bfloat16* as = As + st * T_TILE;
        __nv_bfloat16* bs = Bs + st * T_TILE;
#pragma unroll
        for (int q = 0; q < 2; q++) {
            int c = t + q * 256;           // 0..511
            int row = c >> 2, ce = (c & 3) * 8;
            int grow = bm + row;
            int sz = (grow < M) ? 16 : 0;
            if (grow >= M) grow = M - 1;
            cpa16(&as[row * T_STRIDE + ce], A  + (size_t)grow * K + kt * 32 + ce, sz);
            cpa16(&bs[row * T_STRIDE + ce], Bt + (size_t)(bn + row) * K + kt * 32 + ce, 16);
        }
    };

    // precomputed ldmatrix lane addresses (stage 0, k-step 0)
    const int q = lane >> 3, r = lane & 7;
    const uint32_t as0 = (uint32_t)__cvta_generic_to_shared(As);
    const uint32_t bs0 = (uint32_t)__cvta_generic_to_shared(Bs);
    uint32_t a_addr[4], b_addr[2];
#pragma unroll
    for (int mt = 0; mt < 4; mt++) {
        int row = wm + mt * 16 + r + ((q & 1) << 3);
        int col = (q >> 1) << 3;
        a_addr[mt] = as0 + (row * T_STRIDE + col) * 2;
    }
#pragma unroll
    for (int p = 0; p < 2; p++) {
        int row = wn + ((p * 2 + (q >> 1)) << 3) + r;
        int col = (q & 1) << 3;
        b_addr[p] = bs0 + (row * T_STRIDE + col) * 2;
    }

    float acc[4][4][4];
#pragma unroll
    for (int i = 0; i < 4; i++)
#pragma unroll
        for (int j = 0; j < 4; j++)
#pragma unroll
            for (int z = 0; z < 4; z++) acc[i][j][z] = 0.f;

#pragma unroll
    for (int s = 0; s < GSTAGES - 1; s++) {
        if (s < kTiles) issue_tile(s, s);
        cpa_commit();
    }

    for (int kt = 0; kt < kTiles; kt++) {
        cpa_wait<GSTAGES - 2>();
        __syncthreads();

        int nt = kt + GSTAGES - 1;
        if (nt < kTiles) issue_tile(nt, nt % GSTAGES);
        cpa_commit();

        const uint32_t soff = (uint32_t)((kt % GSTAGES) * STAGE_BYTES);

#pragma unroll
        for (int ks = 0; ks < 2; ks++) {
            const uint32_t ko = soff + ks * 32;    // +16 elems = 32 B
            uint32_t af[4][4], bf[4][2];
#pragma unroll
            for (int mt = 0; mt < 4; mt++)
                ldsm_x4(af[mt][0], af[mt][1], af[mt][2], af[mt][3], a_addr[mt] + ko);
#pragma unroll
            for (int p = 0; p < 2; p++)
                ldsm_x4(bf[p * 2][0], bf[p * 2][1], bf[p * 2 + 1][0], bf[p * 2 + 1][1],
                        b_addr[p] + ko);
#pragma unroll
            for (int mt = 0; mt < 4; mt++) {
#pragma unroll
                for (int ntile = 0; ntile < 4; ntile++) {
                    asm volatile(
                        "mma.sync.aligned.m16n8k16.row.col.f32.bf16.bf16.f32 "
                        "{%0,%1,%2,%3}, {%4,%5,%6,%7}, {%8,%9}, {%0,%1,%2,%3};\n"
                        : "+f"(acc[mt][ntile][0]), "+f"(acc[mt][ntile][1]),
                          "+f"(acc[mt][ntile][2]), "+f"(acc[mt][ntile][3])
                        : "r"(af[mt][0]), "r"(af[mt][1]), "r"(af[mt][2]), "r"(af[mt][3]),
                          "r"(bf[ntile][0]), "r"(bf[ntile][1]));
                }
            }
        }
        __syncthreads();
    }

    // ---- epilogue 1: store C tile (bf16) ----
#pragma unroll
    for (int mt = 0; mt < 4; mt++) {
        int r0 = bm + wm + mt * 16 + gid;
#pragma unroll
        for (int ntile = 0; ntile < 4; ntile++) {
            int c = bn + wn + ntile * 8 + 2 * tg;
            if (r0 < M) {
                __nv_bfloat162 p =
                    __floats2bfloat162_rn(acc[mt][ntile][0], acc[mt][ntile][1]);
                *(uint32_t*)&C[(size_t)r0 * N + c] = *(uint32_t*)&p;
            }
            if (r0 + 8 < M) {
                __nv_bfloat162 p =
                    __floats2bfloat162_rn(acc[mt][ntile][2], acc[mt][ntile][3]);
                *(uint32_t*)&C[(size_t)(r0 + 8) * N + c] = *(uint32_t*)&p;
            }
        }
    }

    // ---- epilogue 2: fused attention dots ----
    float* s_red = (float*)smem_h;
    s_red[t] = 0.f;
    __syncthreads();

    const float* asv = a_s + head * 128;
    const float* adv = a_d + head * 128;
    float csa[8], cda[8];
#pragma unroll
    for (int ntile = 0; ntile < 4; ntile++) {
        int c = wn + ntile * 8 + 2 * tg;
        csa[ntile * 2]     = asv[c];
        csa[ntile * 2 + 1] = asv[c + 1];
        cda[ntile * 2]     = adv[c];
        cda[ntile * 2 + 1] = adv[c + 1];
    }
#pragma unroll
    for (int mt = 0; mt < 4; mt++) {
#pragma unroll
        for (int half = 0; half < 2; half++) {
            float rs = 0.f, rd = 0.f;
#pragma unroll
            for (int ntile = 0; ntile < 4; ntile++) {
                rs = fmaf(acc[mt][ntile][half * 2],     csa[ntile * 2],     rs);
                rs = fmaf(acc[mt][ntile][half * 2 + 1], csa[ntile * 2 + 1], rs);
                rd = fmaf(acc[mt][ntile][half * 2],     cda[ntile * 2],     rd);
                rd = fmaf(acc[mt][ntile][half * 2 + 1], cda[ntile * 2 + 1], rd);
            }
            rs += __shfl_xor_sync(0xffffffffu, rs, 1);
            rs += __shfl_xor_sync(0xffffffffu, rs, 2);
            rd += __shfl_xor_sync(0xffffffffu, rd, 1);
            rd += __shfl_xor_sync(0xffffffffu, rd, 2);
            if (tg == 0) {
                int rl = wm + mt * 16 + half * 8 + gid;
                atomicAdd(&s_red[rl * 2],     rs);
                atomicAdd(&s_red[rl * 2 + 1], rd);
            }
        }
    }
    __syncthreads();
    if (t < 128 && bm + t < M) {
        g_als[(bm + t) * H + head] = s_red[t * 2];
        g_ald[(bm + t) * H + head] = s_red[t * 2 + 1];
    }
}

// ---------------- fused GAT softmax + aggregation, H=8 ---------------------
__global__ __launch_bounds__(256) void gat_fused8_k(
    const __nv_bfloat16* __restrict__ hw, const float* __restrict__ b,
    __nv_bfloat16* __restrict__ act)
{
    __shared__ float s_max[8], s_sum[8], s_ald[8];
    __shared__ float s_alpha[32][8];
    __shared__ int   s_srcs[32];

    const int d = blockIdx.x;
    const int t = threadIdx.x;
    const int beg = g_rowptr[d], deg = g_rowptr[d + 1] - beg;
    const int w = t >> 5, lane = t & 31;
    const int h = t & 7, j = t >> 3;

    if (t < 8) s_ald[t] = g_ald[d * 8 + t];

    {
        const float ald = g_ald[d * 8 + w];
        float m = -INFINITY;
        for (int i = lane; i < deg; i += 32) {
            int s = g_csrc[beg + i];
            float v = g_als[s * 8 + w] + ald;
            v = v > 0.f ? v : 0.2f * v;
            m = fmaxf(m, v);
        }
#pragma unroll
        for (int o = 16; o; o >>= 1)
            m = fmaxf(m, __shfl_xor_sync(0xffffffffu, m, o));
        float sum = 0.f;
        for (int i = lane; i < deg; i += 32) {
            int s = g_csrc[beg + i];
            float v = g_als[s * 8 + w] + ald;
            v = v > 0.f ? v : 0.2f * v;
            sum += __expf(v - m);
        }
#pragma unroll
        for (int o = 16; o; o >>= 1)
            sum += __shfl_xor_sync(0xffffffffu, sum, o);
        if (lane == 0) { s_max[w] = m; s_sum[w] = sum; }
    }
    __syncthreads();

    const int hh = t >> 5;
    float4 a = make_float4(0.f, 0.f, 0.f, 0.f);
    for (int c0 = 0; c0 < deg; c0 += 32) {
        int cn = min(32, deg - c0);
        if (j < cn) {
            int s = g_csrc[beg + c0 + j];
            if (h == 0) s_srcs[j] = s;
            float v = g_als[s * 8 + h] + s_ald[h];
            v = v > 0.f ? v : 0.2f * v;
            s_alpha[j][h] = __expf(v - s_max[h]) / s_sum[h];
        }
        __syncthreads();
        for (int i = 0; i < cn; i++) {
            uint2 hv = *(const uint2*)(hw + (size_t)s_srcs[i] * 1024 + 4 * t);
            float2 f0 = __bfloat1622float2(*(__nv_bfloat162*)&hv.x);
            float2 f1 = __bfloat1622float2(*(__nv_bfloat162*)&hv.y);
            const float al = s_alpha[i][hh];
            a.x = fmaf(f0.x, al, a.x);
            a.y = fmaf(f0.y, al, a.y);
            a.z = fmaf(f1.x, al, a.z);
            a.w = fmaf(f1.y, al, a.w);
        }
        __syncthreads();
    }

    const float4 bv = ((const float4*)b)[t];
    a.x = fmaxf(a.x + bv.x, 0.f);
    a.y = fmaxf(a.y + bv.y, 0.f);
    a.z = fmaxf(a.z + bv.z, 0.f);
    a.w = fmaxf(a.w + bv.w, 0.f);
    __nv_bfloat162 p0 = __floats2bfloat162_rn(a.x, a.y);
    __nv_bfloat162 p1 = __floats2bfloat162_rn(a.z, a.w);
    uint2 packed = make_uint2(*(uint32_t*)&p0, *(uint32_t*)&p1);
    *(uint2*)&act[(size_t)d * 1024 + 4 * t] = packed;
}

// ---------------- fused GAT softmax + aggregation, H=1 (fp32 out) ----------
__global__ __launch_bounds__(128) void gat_fused1_k(
    const __nv_bfloat16* __restrict__ hw, const float* __restrict__ b,
    float* __restrict__ out)
{
    __shared__ float red[128];
    __shared__ float s_alpha[32];
    __shared__ int   s_srcs[32];

    const int d = blockIdx.x;
    const int t = threadIdx.x;
    const int beg = g_rowptr[d], deg = g_rowptr[d + 1] - beg;
    const float ald = g_ald[d];

    float m = -INFINITY;
    for (int i = t; i < deg; i += 128) {
        float v = g_als[g_csrc[beg + i]] + ald;
        v = v > 0.f ? v : 0.2f * v;
        m = fmaxf(m, v);
    }
    red[t] = m; __syncthreads();
#pragma unroll
    for (int off = 64; off >= 1; off >>= 1) {
        if (t < off) red[t] = fmaxf(red[t], red[t + off]);
        __syncthreads();
    }
    const float mx = red[0];
    __syncthreads();

    float sum = 0.f;
    for (int i = t; i < deg; i += 128) {
        float v = g_als[g_csrc[beg + i]] + ald;
        v = v > 0.f ? v : 0.2f * v;
        sum += __expf(v - mx);
    }
    red[t] = sum; __syncthreads();
#pragma unroll
    for (int off = 64; off >= 1; off >>= 1) {
        if (t < off) red[t] += red[t + off];
        __syncthreads();
    }
    const float sm = red[0];
    __syncthreads();

    float acc = 0.f;
    for (int c0 = 0; c0 < deg; c0 += 32) {
        int cn = min(32, deg - c0);
        if (t < cn) {
            int s = g_csrc[beg + c0 + t];
            s_srcs[t] = s;
            float v = g_als[s] + ald;
            v = v > 0.f ? v : 0.2f * v;
            s_alpha[t] = __expf(v - mx) / sm;
        }
        __syncthreads();
        for (int i = 0; i < cn; i++)
            acc = fmaf(__bfloat162float(hw[(size_t)s_srcs[i] * 128 + t]),
                       s_alpha[i], acc);
        __syncthreads();
    }
    out[(size_t)d * 128 + t] = acc + b[t];
}

// ---------------- fused pair-MLP scorer ------------------------------------
__global__ __launch_bounds__(128) void mlp_k(
    const float* __restrict__ h3, const int* __restrict__ liq,
    const int* __restrict__ ing,
    const float* __restrict__ mw1, const float* __restrict__ mb1,
    const float* __restrict__ mw2, const float* __restrict__ mb2,
    const float* __restrict__ mw3, const float* __restrict__ mb3,
    float* __restrict__ outp)
{
    __shared__ float pair[256];
    __shared__ float z1[128];
    __shared__ float z2[64];
    int row = blockIdx.x, t = threadIdx.x;
    int L = liq[row], I = ing[row];
    pair[t]       = h3[(size_t)L * 128 + t];
    pair[128 + t] = h3[(size_t)I * 128 + t];
    __syncthreads();
    float acc = mb1[t];
#pragma unroll 8
    for (int i = 0; i < 256; i++) acc = fmaf(pair[i], mw1[i * 128 + t], acc);
    z1[t] = fmaxf(acc, 0.f);
    __syncthreads();
    if (t < 64) {
        float a2 = mb2[t];
#pragma unroll 8
        for (int i = 0; i < 128; i++) a2 = fmaf(z1[i], mw2[i * 64 + t], a2);
        z2[t] = fmaxf(a2, 0.f);
    }
    __syncthreads();
    if (t < 32) {
        float a3 = fmaf(z2[t], mw3[t], z2[t + 32] * mw3[t + 32]);
#pragma unroll
        for (int o = 16; o; o >>= 1) a3 += __shfl_down_sync(0xffffffffu, a3, o);
        if (t == 0) outp[row] = 1.f / (1.f + expf(-(a3 + mb3[0])));
    }
}

extern "C" void kernel_launch(void* const* d_in, const int* in_sizes, int n_in,
                              void* d_out, int out_size)
{
    const float* x   = (const float*)d_in[0];
    const int*   ei  = (const int*)d_in[1];
    const int*   liq = (const int*)d_in[2];
    const int*   ing = (const int*)d_in[3];
    const float* W1  = (const float*)d_in[4];
    const float* as1 = (const float*)d_in[5];
    const float* ad1 = (const float*)d_in[6];
    const float* b1  = (const float*)d_in[7];
    const float* W2  = (const float*)d_in[8];
    const float* as2 = (const float*)d_in[9];
    const float* ad2 = (const float*)d_in[10];
    const float* b2  = (const float*)d_in[11];
    const float* W3  = (const float*)d_in[12];
    const float* as3 = (const float*)d_in[13];
    const float* ad3 = (const float*)d_in[14];
    const float* b3  = (const float*)d_in[15];
    const float* mw1 = (const float*)d_in[16];
    const float* mb1 = (const float*)d_in[17];
    const float* mw2 = (const float*)d_in[18];
    const float* mb2 = (const float*)d_in[19];
    const float* mw3 = (const float*)d_in[20];
    const float* mb3 = (const float*)d_in[21];
    float* outp = (float*)d_out;

    cudaFuncSetAttribute(mma_gemm_k,
                         cudaFuncAttributeMaxDynamicSharedMemorySize,
                         GEMM_SMEM_BYTES);

    float* bufC;
    __nv_bfloat16 *hw, *act, *xb, *wt1, *wt2, *wt3;
    cudaGetSymbolAddress((void**)&hw,   g_hw);
    cudaGetSymbolAddress((void**)&bufC, g_bufC);
    cudaGetSymbolAddress((void**)&act,  g_act);
    cudaGetSymbolAddress((void**)&xb,   g_xb);
    cudaGetSymbolAddress((void**)&wt1,  g_wt1);
    cudaGetSymbolAddress((void**)&wt2,  g_wt2);
    cudaGetSymbolAddress((void**)&wt3,  g_wt3);

    cvt_all_k<<<(SEG3 + 255) / 256, 256>>>(x, W1, W2, W3);

    build_hist_k<<<(E_TOT + 255) / 256, 256>>>(ei);
    scan1_k<<<NBLK, 1024>>>();
    scan2_k<<<1, 32>>>();
    scan3_k<<<NBLK, 1024>>>();
    scatter_k<<<(E_TOT + 255) / 256, 256>>>();

    dim3 grid8(8, (N_NODES + 127) / 128);
    dim3 grid1(1, (N_NODES + 127) / 128);

    mma_gemm_k<<<grid8, 256, GEMM_SMEM_BYTES>>>(xb, wt1, hw, N_NODES, 1024, 64,
                                                as1, ad1, 8);
    gat_fused8_k<<<N_NODES, 256>>>(hw, b1, act);

    mma_gemm_k<<<grid8, 256, GEMM_SMEM_BYTES>>>(act, wt2, hw, N_NODES, 1024, 1024,
                                                as2, ad2, 8);
    gat_fused8_k<<<N_NODES, 256>>>(hw, b2, act);

    mma_gemm_k<<<grid1, 256, GEMM_SMEM_BYTES>>>(act, wt3, hw, N_NODES, 128, 1024,
                                                as3, ad3, 1);
    gat_fused1_k<<<N_NODES, 128>>>(hw, b3, bufC);

    mlp_k<<<4096, 128>>>(bufC, liq, ing, mw1, mb1, mw2, mb2, mw3, mb3, outp);
}